// round 9
// baseline (speedup 1.0000x reference)
#include <cuda_runtime.h>
#include <cuda_bf16.h>
#include <math.h>
#include <stdint.h>

#define NCAM 6
#define MID 256
#define DBINS 112
#define HH 32
#define WW 88
#define NPIX 2816
#define NVOX (128*128*16)
#define WHT 576

__device__ __align__(1024) float g_xf [NCAM*NPIX*MID];
__device__ __align__(1024) float g_dp [NCAM*DBINS*NPIX];
__device__ __align__(1024) float g_gate[NCAM*MID];
__device__ __align__(1024) __nv_bfloat16 g_imgh[NCAM*NPIX*512];
__device__ __align__(1024) __nv_bfloat16 g_imgl[NCAM*NPIX*512];
__device__ __align__(1024) __nv_bfloat16 g_xh[NCAM*NPIX*MID];
__device__ __align__(1024) __nv_bfloat16 g_xl[NCAM*NPIX*MID];
__device__ __align__(1024) __nv_bfloat16 g_yh[NCAM*NPIX*MID];
__device__ __align__(1024) __nv_bfloat16 g_yl[NCAM*NPIX*MID];
__device__ __align__(1024) __nv_bfloat16 g_Wh[WHT*128*64];
__device__ __align__(1024) __nv_bfloat16 g_Wl[WHT*128*64];

__device__ __forceinline__ uint32_t smem_u32(const void* p) {
    uint32_t a;
    asm("{ .reg .u64 t; cvta.to.shared.u64 t, %1; cvt.u32.u64 %0, t; }" : "=r"(a) : "l"(p));
    return a;
}
#define SW128(o) ((o) ^ (((o) >> 3) & 0x70))
#define LDM4(r0,r1,r2,r3,addr) \
    asm volatile("ldmatrix.sync.aligned.m8n8.x4.shared.b16 {%0,%1,%2,%3}, [%4];" \
        : "=r"(r0),"=r"(r1),"=r"(r2),"=r"(r3) : "r"(addr))
#define MMA(d,a,b0,b1) \
    asm volatile("mma.sync.aligned.m16n8k16.row.col.f32.bf16.bf16.f32 " \
        "{%0,%1,%2,%3},{%4,%5,%6,%7},{%8,%9},{%0,%1,%2,%3};" \
        : "+f"((d)[0]),"+f"((d)[1]),"+f"((d)[2]),"+f"((d)[3]) \
        : "r"((a)[0]),"r"((a)[1]),"r"((a)[2]),"r"((a)[3]),"r"(b0),"r"(b1))
__device__ __forceinline__ void cpa16(uint32_t dst, const void* src, int sz) {
    asm volatile("cp.async.cg.shared.global [%0], [%1], 16, %2;" :: "r"(dst), "l"(src), "r"(sz) : "memory");
}
#define CPA_COMMIT() asm volatile("cp.async.commit_group;" ::: "memory")

__global__ __launch_bounds__(256) void prep_img_kernel(const float* __restrict__ img)
{
    __shared__ float st[32][128];
    const int px0 = blockIdx.x * 128, cg = blockIdx.y, cam = blockIdx.z;
    const int tid = threadIdx.x;
    for (int i = tid; i < 32*128; i += 256) {
        const int c = i >> 7, p = i & 127;
        st[c][p] = img[((size_t)cam*512 + cg*32 + c)*NPIX + px0 + p];
    }
    __syncthreads();
    for (int i = tid; i < 128*32; i += 256) {
        const int p = i >> 5, c = i & 31;
        float v = st[c][p];
        __nv_bfloat16 h = __float2bfloat16(v);
        __nv_bfloat16 l = __float2bfloat16(v - __bfloat162float(h));
        const size_t o = ((size_t)(cam*NPIX + px0 + p))*512 + cg*32 + c;
        g_imgh[o] = h; g_imgl[o] = l;
    }
}

__global__ __launch_bounds__(256) void wtrans_kernel(const float* __restrict__ red_w,
                                                     const float* __restrict__ bb_w)
{
    const int idx = blockIdx.x*256 + threadIdx.x;
    if (idx >= WHT*128*64) return;
    const int r = idx >> 6, ci = idx & 63;
    const int ht = r >> 7, ocl = r & 127;
    float w;
    if (ht < 144) {
        const int g = ht >> 1, half = ht & 1, tap = g >> 3, cig = g & 7;
        w = red_w[((size_t)(half*128 + ocl)*512 + cig*64 + ci)*9 + tap];
    } else {
        const int h2 = ht - 144, layer = h2 / 72, rr = h2 % 72;
        const int g = rr >> 1, half = rr & 1, tap = g >> 2, cig = g & 3;
        w = bb_w[(size_t)layer*589824 + ((size_t)(half*128 + ocl)*256 + cig*64 + ci)*9 + tap];
    }
    __nv_bfloat16 h = __float2bfloat16(w);
    __nv_bfloat16 l = __float2bfloat16(w - __bfloat162float(h));
    const size_t off = (size_t)ht*16384 + SW128((uint32_t)(ocl*128 + ci*2));
    *(uint16_t*)((char*)g_Wh + off) = __bfloat16_as_ushort(h);
    *(uint16_t*)((char*)g_Wl + off) = __bfloat16_as_ushort(l);
}

__global__ void gate_kernel(const float* __restrict__ intr,
                            const float* __restrict__ w1, const float* __restrict__ b1,
                            const float* __restrict__ w2, const float* __restrict__ b2,
                            const float* __restrict__ rw, const float* __restrict__ rb,
                            const float* __restrict__ ew, const float* __restrict__ eb,
                            float* __restrict__ gate)
{
    int cam = blockIdx.x, tid = threadIdx.x;
    __shared__ float sp_s, h[256], h2[256], t[256];
    if (tid == 0) {
        double A[4][8];
        for (int r = 0; r < 4; r++) {
            for (int c = 0; c < 4; c++) A[r][c] = (double)intr[cam*16 + r*4 + c];
            for (int c = 0; c < 4; c++) A[r][4+c] = (r == c) ? 1.0 : 0.0;
        }
        for (int col = 0; col < 4; col++) {
            int piv = col; double best = fabs(A[col][col]);
            for (int r = col+1; r < 4; r++)
                if (fabs(A[r][col]) > best) { best = fabs(A[r][col]); piv = r; }
            if (piv != col)
                for (int c = 0; c < 8; c++) { double tmp = A[col][c]; A[col][c] = A[piv][c]; A[piv][c] = tmp; }
            double d = A[col][col];
            for (int c = 0; c < 8; c++) A[col][c] /= d;
            for (int r = 0; r < 4; r++) if (r != col) {
                double f = A[r][col];
                for (int c = 0; c < 8; c++) A[r][c] -= f * A[col][c];
            }
        }
        sp_s = (float)(1000.0 * sqrt(A[0][4]*A[0][4] + A[1][5]*A[1][5]));
    }
    __syncthreads();
    float sp = sp_s;
    h[tid] = fmaxf(sp * w1[tid] + b1[tid], 0.f);
    __syncthreads();
    float s = b2[tid];
    for (int k = 0; k < 256; k++) s += h[k] * w2[k*256 + tid];
    h2[tid] = s;
    __syncthreads();
    s = rb[tid];
    for (int c = 0; c < 256; c++) s += rw[tid*256 + c] * h2[c];
    t[tid] = fmaxf(s, 0.f);
    __syncthreads();
    s = eb[tid];
    for (int c = 0; c < 256; c++) s += ew[tid*256 + c] * t[c];
    gate[cam*256 + tid] = 1.f / (1.f + __expf(-s));
}

// HMMA conv, 3-stage cp.async pipeline. Block 128px x 128oc, grid (22,2,6).
// MODE 0: relu*gate -> f32+split; 1: relu -> split; 2: relu(res+) -> f32+split; 3: like 2 no split
#define BUF 65536
#define CONV_SMEM (2048 + 3*BUF)
template<int CIN, int MODE>
__global__ void __launch_bounds__(256, 1)
conv_kernel(const __nv_bfloat16* __restrict__ inh, const __nv_bfloat16* __restrict__ inl,
            int aoff,
            const float* __restrict__ scale, const float* __restrict__ bias,
            const float* __restrict__ gate,  const float* res,
            float* outf, __nv_bfloat16* __restrict__ outh, __nv_bfloat16* __restrict__ outl)
{
    constexpr int CIG = CIN / 64, NCH = 9 * CIG;
    extern __shared__ __align__(1024) char smem[];
    float* s_sc = (float*)smem;
    float* s_bi = (float*)(smem + 512);
    float* s_gt = (float*)(smem + 1024);
    const uint32_t sb0 = smem_u32(smem) + 2048;

    const int pxt = blockIdx.x, och = blockIdx.y, cam = blockIdx.z;
    const int tid = threadIdx.x, wid = tid >> 5, lane = tid & 31;
    const int wm = wid & 3, wn = wid >> 2;
    const int g = lane >> 2, tig = lane & 3;

    if (tid < 128) {
        s_sc[tid] = scale[och*128 + tid];
        s_bi[tid] = bias [och*128 + tid];
        s_gt[tid] = (MODE == 0) ? gate[cam*256 + och*128 + tid] : 0.f;
    }

    float acc[2][8][4];
    #pragma unroll
    for (int a = 0; a < 2; a++)
        #pragma unroll
        for (int b = 0; b < 8; b++)
            #pragma unroll
            for (int c = 0; c < 4; c++) acc[a][b][c] = 0.f;

    const int arow = wm*32 + (lane & 15);
    const int ak16 = (lane >> 4) << 4;
    const int brow = wn*64 + (lane & 7) + ((lane >> 4) << 3);
    const int bk16 = ((lane >> 3) & 1) << 4;

    auto stage = [&](int j, int b) {
        const uint32_t dA = sb0 + b*BUF, dB = dA + 32768;
        const size_t ht = (size_t)(aoff + j*2 + och) * 16384;
        const char* sH = (const char*)g_Wh + ht;
        const char* sL = (const char*)g_Wl + ht;
        #pragma unroll
        for (int t = 0; t < 4; t++) {
            const uint32_t o = (tid + 256*t) * 16;
            cpa16(dB + o,         sH + o, 16);
            cpa16(dB + 16384 + o, sL + o, 16);
        }
        const int tap = j / CIG, cig = j - tap*CIG;
        const int dh = tap/3 - 1, dw = tap%3 - 1;
        #pragma unroll
        for (int t = 0; t < 4; t++) {
            const int u = tid + 256*t;
            const int px = u >> 3, q = u & 7;
            const int p = pxt*128 + px;
            const int h = p/88 + dh, w = p - (p/88)*88 + dw;
            const bool ok = ((unsigned)h < 32u) & ((unsigned)w < 88u);
            const size_t s0 = ok ? (((size_t)(cam*NPIX + h*88 + w))*CIN + cig*64 + q*8) : 0;
            const int sz = ok ? 16 : 0;
            const uint32_t sw = SW128((uint32_t)(px*128 + q*16));
            cpa16(dA + sw,         inh + s0, sz);
            cpa16(dA + 16384 + sw, inl + s0, sz);
        }
        CPA_COMMIT();
    };

    stage(0, 0);
    stage(1, 1);
    #pragma unroll 1
    for (int j = 0; j < NCH; j++) {
        const int b = j % 3;
        if (j + 1 < NCH) asm volatile("cp.async.wait_group 1;" ::: "memory");
        else             asm volatile("cp.async.wait_group 0;" ::: "memory");
        __syncthreads();
        if (j + 2 < NCH) stage(j + 2, (j + 2) % 3);

        const uint32_t sbA = sb0 + b*BUF, sbB = sbA + 32768;
        #pragma unroll
        for (int ks = 0; ks < 4; ks++) {
            uint32_t ah[2][4], al[2][4], bh[4][4], bl[4][4];
            #pragma unroll
            for (int mt = 0; mt < 2; mt++) {
                const uint32_t off = (uint32_t)((arow + mt*16)*128 + ks*32) + ak16;
                LDM4(ah[mt][0],ah[mt][1],ah[mt][2],ah[mt][3], sbA + SW128(off));
                LDM4(al[mt][0],al[mt][1],al[mt][2],al[mt][3], sbA + 16384 + SW128(off));
            }
            #pragma unroll
            for (int np = 0; np < 4; np++) {
                const uint32_t off = (uint32_t)((brow + np*16)*128 + ks*32) + bk16;
                LDM4(bh[np][0],bh[np][1],bh[np][2],bh[np][3], sbB + SW128(off));
                LDM4(bl[np][0],bl[np][1],bl[np][2],bl[np][3], sbB + 16384 + SW128(off));
            }
            #pragma unroll
            for (int mt = 0; mt < 2; mt++)
                #pragma unroll
                for (int np = 0; np < 4; np++) {
                    MMA(acc[mt][np*2],   ah[mt], bh[np][0], bh[np][1]);
                    MMA(acc[mt][np*2+1], ah[mt], bh[np][2], bh[np][3]);
                    MMA(acc[mt][np*2],   ah[mt], bl[np][0], bl[np][1]);
                    MMA(acc[mt][np*2+1], ah[mt], bl[np][2], bl[np][3]);
                    MMA(acc[mt][np*2],   al[mt], bh[np][0], bh[np][1]);
                    MMA(acc[mt][np*2+1], al[mt], bh[np][2], bh[np][3]);
                }
        }
    }

    const int pxb = pxt*128 + wm*32;
    #pragma unroll
    for (int mt = 0; mt < 2; mt++)
        #pragma unroll
        for (int nt = 0; nt < 8; nt++) {
            const int ocl = wn*64 + nt*8 + 2*tig;
            const float2 sc = *(float2*)&s_sc[ocl];
            const float2 bi = *(float2*)&s_bi[ocl];
            #pragma unroll
            for (int r = 0; r < 2; r++) {
                const int px = pxb + mt*16 + g + r*8;
                float vx = acc[mt][nt][r*2]   * sc.x + bi.x;
                float vy = acc[mt][nt][r*2+1] * sc.y + bi.y;
                const size_t base = (size_t)(cam*NPIX + px)*256 + och*128 + ocl;
                if (MODE == 0) {
                    const float2 gt = *(float2*)&s_gt[ocl];
                    vx = fmaxf(vx, 0.f)*gt.x; vy = fmaxf(vy, 0.f)*gt.y;
                    *(float2*)&outf[base] = make_float2(vx, vy);
                } else if (MODE == 1) {
                    vx = fmaxf(vx, 0.f); vy = fmaxf(vy, 0.f);
                } else {
                    const float2 r0 = *(const float2*)&res[base];
                    vx = fmaxf(vx + r0.x, 0.f); vy = fmaxf(vy + r0.y, 0.f);
                    *(float2*)&outf[base] = make_float2(vx, vy);
                }
                if (MODE != 3) {
                    const __nv_bfloat16 h0 = __float2bfloat16(vx), h1 = __float2bfloat16(vy);
                    const uint32_t hp = (uint32_t)__bfloat16_as_ushort(h0)
                                      | ((uint32_t)__bfloat16_as_ushort(h1) << 16);
                    const uint32_t lp =
                          (uint32_t)__bfloat16_as_ushort(__float2bfloat16(vx - __bfloat162float(h0)))
                        | ((uint32_t)__bfloat16_as_ushort(__float2bfloat16(vy - __bfloat162float(h1))) << 16);
                    *(uint32_t*)&outh[base] = hp;
                    *(uint32_t*)&outl[base] = lp;
                }
            }
        }
}

__global__ __launch_bounds__(128)
void depth_softmax_kernel(const float* __restrict__ x,
                          const float* __restrict__ w, const float* __restrict__ b,
                          float* __restrict__ dp)
{
    const int pix = blockIdx.x, cam = pix / NPIX, p = pix % NPIX;
    const int tid = threadIdx.x;
    __shared__ float sx[256], red[128];
    const float* xc = x + (size_t)pix * 256;
    sx[tid] = xc[tid]; sx[tid+128] = xc[tid+128];
    __syncthreads();
    float lg = -1e30f;
    if (tid < DBINS) {
        float a0 = 0.f, a1 = 0.f, a2 = 0.f, a3 = 0.f;
        const float* wr = w + tid*256;
        #pragma unroll 4
        for (int c = 0; c < 256; c += 4) {
            const float4 xv = *(const float4*)&sx[c];
            const float4 wv = *(const float4*)&wr[c];
            a0 = fmaf(xv.x, wv.x, a0); a1 = fmaf(xv.y, wv.y, a1);
            a2 = fmaf(xv.z, wv.z, a2); a3 = fmaf(xv.w, wv.w, a3);
        }
        lg = (a0 + a1) + (a2 + a3) + b[tid];
    }
    red[tid] = lg; __syncthreads();
    for (int off = 64; off > 0; off >>= 1) {
        if (tid < off) red[tid] = fmaxf(red[tid], red[tid+off]);
        __syncthreads();
    }
    const float m = red[0]; __syncthreads();
    float e = (tid < DBINS) ? __expf(lg - m) : 0.f;
    red[tid] = e; __syncthreads();
    for (int off = 64; off > 0; off >>= 1) {
        if (tid < off) red[tid] += red[tid+off];
        __syncthreads();
    }
    const float inv = 1.f / red[0];
    if (tid < DBINS) dp[((size_t)cam*DBINS + tid)*NPIX + p] = e * inv;
}

__global__ __launch_bounds__(256)
void sample_kernel(const float* __restrict__ grid, const float* __restrict__ dp,
                   float* __restrict__ out)
{
    const int v = blockIdx.x * blockDim.x + threadIdx.x;
    if (v >= NVOX) return;
    float agg = 0.f, mask = 0.f;
    #pragma unroll 1
    for (int cam = 0; cam < NCAM; cam++) {
        const float* g = grid + ((size_t)cam * NVOX + v) * 3;
        const float ix = ((g[0] + 1.f) * 88.f  - 1.f) * 0.5f;
        const float iy = ((g[1] + 1.f) * 32.f  - 1.f) * 0.5f;
        const float iz = ((g[2] + 1.f) * 112.f - 1.f) * 0.5f;
        const float fx0 = floorf(ix), fy0 = floorf(iy), fz0 = floorf(iz);
        const float fx = ix - fx0, fy = iy - fy0, fz = iz - fz0;
        const int x0 = (int)fx0, y0 = (int)fy0, z0 = (int)fz0;
        const float* dc = dp + (size_t)cam * DBINS * NPIX;
        #pragma unroll
        for (int dz = 0; dz < 2; dz++)
            #pragma unroll
            for (int dy = 0; dy < 2; dy++)
                #pragma unroll
                for (int dx = 0; dx < 2; dx++) {
                    const int xi = x0 + dx, yi = y0 + dy, zi = z0 + dz;
                    const float wv = (dx ? fx : 1.f-fx) * (dy ? fy : 1.f-fy) * (dz ? fz : 1.f-fz);
                    if (xi >= 0 && xi < WW && yi >= 0 && yi < HH && zi >= 0 && zi < DBINS) {
                        agg  += wv * dc[(size_t)zi*NPIX + yi*WW + xi];
                        mask += wv;
                    }
                }
    }
    out[v] = (mask > 0.f) ? (agg / mask) : agg;
}

extern "C" void kernel_launch(void* const* d_in, const int* in_sizes, int n_in,
                              void* d_out, int out_size)
{
    const float* img    = (const float*)d_in[0];
    const float* intr   = (const float*)d_in[1];
    const float* grid   = (const float*)d_in[2];
    const float* red_w  = (const float*)d_in[3];
    const float* red_s  = (const float*)d_in[4];
    const float* red_b  = (const float*)d_in[5];
    const float* mlp_w1 = (const float*)d_in[6];
    const float* mlp_b1 = (const float*)d_in[7];
    const float* mlp_w2 = (const float*)d_in[8];
    const float* mlp_b2 = (const float*)d_in[9];
    const float* se_rw  = (const float*)d_in[10];
    const float* se_rb  = (const float*)d_in[11];
    const float* se_ew  = (const float*)d_in[12];
    const float* se_eb  = (const float*)d_in[13];
    const float* bb_w   = (const float*)d_in[14];
    const float* bb_s   = (const float*)d_in[15];
    const float* bb_b   = (const float*)d_in[16];
    const float* dp_w   = (const float*)d_in[17];
    const float* dp_b   = (const float*)d_in[18];

    float *pxf, *pdp, *pg;
    __nv_bfloat16 *pih, *pil, *pxh, *pxl, *pyh, *pyl;
    cudaGetSymbolAddress((void**)&pxf, g_xf);
    cudaGetSymbolAddress((void**)&pdp, g_dp);
    cudaGetSymbolAddress((void**)&pg,  g_gate);
    cudaGetSymbolAddress((void**)&pih, g_imgh);
    cudaGetSymbolAddress((void**)&pil, g_imgl);
    cudaGetSymbolAddress((void**)&pxh, g_xh);
    cudaGetSymbolAddress((void**)&pxl, g_xl);
    cudaGetSymbolAddress((void**)&pyh, g_yh);
    cudaGetSymbolAddress((void**)&pyl, g_yl);

    cudaFuncSetAttribute(conv_kernel<512,0>, cudaFuncAttributeMaxDynamicSharedMemorySize, CONV_SMEM);
    cudaFuncSetAttribute(conv_kernel<256,1>, cudaFuncAttributeMaxDynamicSharedMemorySize, CONV_SMEM);
    cudaFuncSetAttribute(conv_kernel<256,2>, cudaFuncAttributeMaxDynamicSharedMemorySize, CONV_SMEM);
    cudaFuncSetAttribute(conv_kernel<256,3>, cudaFuncAttributeMaxDynamicSharedMemorySize, CONV_SMEM);

    gate_kernel<<<NCAM, 256>>>(intr, mlp_w1, mlp_b1, mlp_w2, mlp_b2,
                               se_rw, se_rb, se_ew, se_eb, pg);
    prep_img_kernel<<<dim3(22, 16, NCAM), 256>>>(img);
    wtrans_kernel<<<(WHT*128*64 + 255)/256, 256>>>(red_w, bb_w);

    dim3 cg(22, 2, NCAM);
    conv_kernel<512,0><<<cg, 256, CONV_SMEM>>>(pih, pil, 0, red_s, red_b, pg,
                                               nullptr, pxf, pxh, pxl);
    for (int i = 0; i < 3; i++) {
        conv_kernel<256,1><<<cg, 256, CONV_SMEM>>>(pxh, pxl, 144 + (2*i)*72,
            bb_s + (2*i)*MID, bb_b + (2*i)*MID, nullptr, nullptr, nullptr, pyh, pyl);
        if (i < 2)
            conv_kernel<256,2><<<cg, 256, CONV_SMEM>>>(pyh, pyl, 144 + (2*i+1)*72,
                bb_s + (2*i+1)*MID, bb_b + (2*i+1)*MID, nullptr, pxf, pxf, pxh, pxl);
        else
            conv_kernel<256,3><<<cg, 256, CONV_SMEM>>>(pyh, pyl, 144 + (2*i+1)*72,
                bb_s + (2*i+1)*MID, bb_b + (2*i+1)*MID, nullptr, pxf, pxf, pxh, pxl);
    }
    depth_softmax_kernel<<<NCAM * NPIX, 128>>>(pxf, dp_w, dp_b, pdp);
    sample_kernel<<<(NVOX + 255)/256, 256>>>(grid, pdp, (float*)d_out);
}

// round 10
// speedup vs baseline: 1.0406x; 1.0406x over previous
#include <cuda_runtime.h>
#include <cuda_bf16.h>
#include <math.h>
#include <stdint.h>

#define NCAM 6
#define MID 256
#define DBINS 112
#define HH 32
#define WW 88
#define NPIX 2816
#define NVOX (128*128*16)
#define WHT 576

__device__ __align__(1024) float g_xf [NCAM*NPIX*MID];
__device__ __align__(1024) float g_dp [NCAM*DBINS*NPIX];
__device__ __align__(1024) float g_gate[NCAM*MID];
__device__ __align__(1024) __nv_bfloat16 g_imgh[NCAM*NPIX*512];
__device__ __align__(1024) __nv_bfloat16 g_imgl[NCAM*NPIX*512];
__device__ __align__(1024) __nv_bfloat16 g_xh[NCAM*NPIX*MID];
__device__ __align__(1024) __nv_bfloat16 g_xl[NCAM*NPIX*MID];
__device__ __align__(1024) __nv_bfloat16 g_yh[NCAM*NPIX*MID];
__device__ __align__(1024) __nv_bfloat16 g_yl[NCAM*NPIX*MID];
__device__ __align__(1024) __nv_bfloat16 g_Wh[WHT*128*64];
__device__ __align__(1024) __nv_bfloat16 g_Wl[WHT*128*64];

__device__ __forceinline__ uint32_t smem_u32(const void* p) {
    uint32_t a;
    asm("{ .reg .u64 t; cvta.to.shared.u64 t, %1; cvt.u32.u64 %0, t; }" : "=r"(a) : "l"(p));
    return a;
}
#define SW128(o) ((o) ^ (((o) >> 3) & 0x70))
#define LDM4(r0,r1,r2,r3,addr) \
    asm volatile("ldmatrix.sync.aligned.m8n8.x4.shared.b16 {%0,%1,%2,%3}, [%4];" \
        : "=r"(r0),"=r"(r1),"=r"(r2),"=r"(r3) : "r"(addr))
#define MMA(d,a,b0,b1) \
    asm volatile("mma.sync.aligned.m16n8k16.row.col.f32.bf16.bf16.f32 " \
        "{%0,%1,%2,%3},{%4,%5,%6,%7},{%8,%9},{%0,%1,%2,%3};" \
        : "+f"((d)[0]),"+f"((d)[1]),"+f"((d)[2]),"+f"((d)[3]) \
        : "r"((a)[0]),"r"((a)[1]),"r"((a)[2]),"r"((a)[3]),"r"(b0),"r"(b1))
__device__ __forceinline__ void cpa16(uint32_t dst, const void* src, int sz) {
    asm volatile("cp.async.cg.shared.global [%0], [%1], 16, %2;" :: "r"(dst), "l"(src), "r"(sz) : "memory");
}
#define CPA_COMMIT() asm volatile("cp.async.commit_group;" ::: "memory")

__global__ __launch_bounds__(256) void prep_img_kernel(const float* __restrict__ img)
{
    __shared__ float st[32][128];
    const int px0 = blockIdx.x * 128, cg = blockIdx.y, cam = blockIdx.z;
    const int tid = threadIdx.x;
    for (int i = tid; i < 32*128; i += 256) {
        const int c = i >> 7, p = i & 127;
        st[c][p] = img[((size_t)cam*512 + cg*32 + c)*NPIX + px0 + p];
    }
    __syncthreads();
    for (int i = tid; i < 128*32; i += 256) {
        const int p = i >> 5, c = i & 31;
        float v = st[c][p];
        __nv_bfloat16 h = __float2bfloat16(v);
        __nv_bfloat16 l = __float2bfloat16(v - __bfloat162float(h));
        const size_t o = ((size_t)(cam*NPIX + px0 + p))*512 + cg*32 + c;
        g_imgh[o] = h; g_imgl[o] = l;
    }
}

__global__ __launch_bounds__(256) void wtrans_kernel(const float* __restrict__ red_w,
                                                     const float* __restrict__ bb_w)
{
    const int idx = blockIdx.x*256 + threadIdx.x;
    if (idx >= WHT*128*64) return;
    const int r = idx >> 6, ci = idx & 63;
    const int ht = r >> 7, ocl = r & 127;
    float w;
    if (ht < 144) {
        const int g = ht >> 1, half = ht & 1, tap = g >> 3, cig = g & 7;
        w = red_w[((size_t)(half*128 + ocl)*512 + cig*64 + ci)*9 + tap];
    } else {
        const int h2 = ht - 144, layer = h2 / 72, rr = h2 % 72;
        const int g = rr >> 1, half = rr & 1, tap = g >> 2, cig = g & 3;
        w = bb_w[(size_t)layer*589824 + ((size_t)(half*128 + ocl)*256 + cig*64 + ci)*9 + tap];
    }
    __nv_bfloat16 h = __float2bfloat16(w);
    __nv_bfloat16 l = __float2bfloat16(w - __bfloat162float(h));
    const size_t off = (size_t)ht*16384 + SW128((uint32_t)(ocl*128 + ci*2));
    *(uint16_t*)((char*)g_Wh + off) = __bfloat16_as_ushort(h);
    *(uint16_t*)((char*)g_Wl + off) = __bfloat16_as_ushort(l);
}

__global__ void gate_kernel(const float* __restrict__ intr,
                            const float* __restrict__ w1, const float* __restrict__ b1,
                            const float* __restrict__ w2, const float* __restrict__ b2,
                            const float* __restrict__ rw, const float* __restrict__ rb,
                            const float* __restrict__ ew, const float* __restrict__ eb,
                            float* __restrict__ gate)
{
    int cam = blockIdx.x, tid = threadIdx.x;
    __shared__ float sp_s, h[256], h2[256], t[256];
    if (tid == 0) {
        double A[4][8];
        for (int r = 0; r < 4; r++) {
            for (int c = 0; c < 4; c++) A[r][c] = (double)intr[cam*16 + r*4 + c];
            for (int c = 0; c < 4; c++) A[r][4+c] = (r == c) ? 1.0 : 0.0;
        }
        for (int col = 0; col < 4; col++) {
            int piv = col; double best = fabs(A[col][col]);
            for (int r = col+1; r < 4; r++)
                if (fabs(A[r][col]) > best) { best = fabs(A[r][col]); piv = r; }
            if (piv != col)
                for (int c = 0; c < 8; c++) { double tmp = A[col][c]; A[col][c] = A[piv][c]; A[piv][c] = tmp; }
            double d = A[col][col];
            for (int c = 0; c < 8; c++) A[col][c] /= d;
            for (int r = 0; r < 4; r++) if (r != col) {
                double f = A[r][col];
                for (int c = 0; c < 8; c++) A[r][c] -= f * A[col][c];
            }
        }
        sp_s = (float)(1000.0 * sqrt(A[0][4]*A[0][4] + A[1][5]*A[1][5]));
    }
    __syncthreads();
    float sp = sp_s;
    h[tid] = fmaxf(sp * w1[tid] + b1[tid], 0.f);
    __syncthreads();
    float s = b2[tid];
    for (int k = 0; k < 256; k++) s += h[k] * w2[k*256 + tid];
    h2[tid] = s;
    __syncthreads();
    s = rb[tid];
    for (int c = 0; c < 256; c++) s += rw[tid*256 + c] * h2[c];
    t[tid] = fmaxf(s, 0.f);
    __syncthreads();
    s = eb[tid];
    for (int c = 0; c < 256; c++) s += ew[tid*256 + c] * t[c];
    gate[cam*256 + tid] = 1.f / (1.f + __expf(-s));
}

// HMMA conv, 16 warps (512 thr), warp tile 32px x 32oc, 3-stage cp.async.
// MODE 0: relu*gate -> f32+split; 1: relu -> split; 2: relu(res+) -> f32+split; 3: like 2 no split
#define BUF 65536
#define CONV_SMEM (2048 + 3*BUF)
template<int CIN, int MODE>
__global__ void __launch_bounds__(512, 1)
conv_kernel(const __nv_bfloat16* __restrict__ inh, const __nv_bfloat16* __restrict__ inl,
            int aoff,
            const float* __restrict__ scale, const float* __restrict__ bias,
            const float* __restrict__ gate,  const float* res,
            float* outf, __nv_bfloat16* __restrict__ outh, __nv_bfloat16* __restrict__ outl)
{
    constexpr int CIG = CIN / 64, NCH = 9 * CIG;
    extern __shared__ __align__(1024) char smem[];
    float* s_sc = (float*)smem;
    float* s_bi = (float*)(smem + 512);
    float* s_gt = (float*)(smem + 1024);
    const uint32_t sb0 = smem_u32(smem) + 2048;

    const int pxt = blockIdx.x, och = blockIdx.y, cam = blockIdx.z;
    const int tid = threadIdx.x, wid = tid >> 5, lane = tid & 31;
    const int wm = wid & 3, wn = wid >> 2;      // 4 x 4 warps
    const int g = lane >> 2, tig = lane & 3;

    if (tid < 128) {
        s_sc[tid] = scale[och*128 + tid];
        s_bi[tid] = bias [och*128 + tid];
        s_gt[tid] = (MODE == 0) ? gate[cam*256 + och*128 + tid] : 0.f;
    }

    float acc[2][4][4];
    #pragma unroll
    for (int a = 0; a < 2; a++)
        #pragma unroll
        for (int b = 0; b < 4; b++)
            #pragma unroll
            for (int c = 0; c < 4; c++) acc[a][b][c] = 0.f;

    const int arow = wm*32 + (lane & 15);
    const int ak16 = (lane >> 4) << 4;
    const int brow = wn*32 + (lane & 7) + ((lane >> 4) << 3);
    const int bk16 = ((lane >> 3) & 1) << 4;

    auto stage = [&](int j, int b) {
        const uint32_t dA = sb0 + b*BUF, dB = dA + 32768;
        const size_t ht = (size_t)(aoff + j*2 + och) * 16384;
        const char* sH = (const char*)g_Wh + ht;
        const char* sL = (const char*)g_Wl + ht;
        #pragma unroll
        for (int t = 0; t < 2; t++) {
            const uint32_t o = (tid + 512*t) * 16;
            cpa16(dB + o,         sH + o, 16);
            cpa16(dB + 16384 + o, sL + o, 16);
        }
        const int tap = j / CIG, cig = j - tap*CIG;
        const int dh = tap/3 - 1, dw = tap%3 - 1;
        #pragma unroll
        for (int t = 0; t < 2; t++) {
            const int u = tid + 512*t;
            const int px = u >> 3, q = u & 7;
            const int p = pxt*128 + px;
            const int h = p/88 + dh, w = p - (p/88)*88 + dw;
            const bool ok = ((unsigned)h < 32u) & ((unsigned)w < 88u);
            const size_t s0 = ok ? (((size_t)(cam*NPIX + h*88 + w))*CIN + cig*64 + q*8) : 0;
            const int sz = ok ? 16 : 0;
            const uint32_t sw = SW128((uint32_t)(px*128 + q*16));
            cpa16(dA + sw,         inh + s0, sz);
            cpa16(dA + 16384 + sw, inl + s0, sz);
        }
        CPA_COMMIT();
    };

    stage(0, 0);
    stage(1, 1);
    #pragma unroll 1
    for (int j = 0; j < NCH; j++) {
        const int b = j % 3;
        if (j + 1 < NCH) asm volatile("cp.async.wait_group 1;" ::: "memory");
        else             asm volatile("cp.async.wait_group 0;" ::: "memory");
        __syncthreads();
        if (j + 2 < NCH) stage(j + 2, (j + 2) % 3);

        const uint32_t sbA = sb0 + b*BUF, sbB = sbA + 32768;
        #pragma unroll
        for (int ks = 0; ks < 4; ks++) {
            uint32_t ah[2][4], al[2][4], bh[2][4], bl[2][4];
            #pragma unroll
            for (int mt = 0; mt < 2; mt++) {
                const uint32_t off = (uint32_t)((arow + mt*16)*128 + ks*32) + ak16;
                LDM4(ah[mt][0],ah[mt][1],ah[mt][2],ah[mt][3], sbA + SW128(off));
                LDM4(al[mt][0],al[mt][1],al[mt][2],al[mt][3], sbA + 16384 + SW128(off));
            }
            #pragma unroll
            for (int np = 0; np < 2; np++) {
                const uint32_t off = (uint32_t)((brow + np*16)*128 + ks*32) + bk16;
                LDM4(bh[np][0],bh[np][1],bh[np][2],bh[np][3], sbB + SW128(off));
                LDM4(bl[np][0],bl[np][1],bl[np][2],bl[np][3], sbB + 16384 + SW128(off));
            }
            #pragma unroll
            for (int mt = 0; mt < 2; mt++)
                #pragma unroll
                for (int np = 0; np < 2; np++) {
                    MMA(acc[mt][np*2],   ah[mt], bh[np][0], bh[np][1]);
                    MMA(acc[mt][np*2+1], ah[mt], bh[np][2], bh[np][3]);
                    MMA(acc[mt][np*2],   ah[mt], bl[np][0], bl[np][1]);
                    MMA(acc[mt][np*2+1], ah[mt], bl[np][2], bl[np][3]);
                    MMA(acc[mt][np*2],   al[mt], bh[np][0], bh[np][1]);
                    MMA(acc[mt][np*2+1], al[mt], bh[np][2], bh[np][3]);
                }
        }
    }

    const int pxb = pxt*128 + wm*32;
    #pragma unroll
    for (int mt = 0; mt < 2; mt++)
        #pragma unroll
        for (int nt = 0; nt < 4; nt++) {
            const int ocl = wn*32 + nt*8 + 2*tig;
            const float2 sc = *(float2*)&s_sc[ocl];
            const float2 bi = *(float2*)&s_bi[ocl];
            #pragma unroll
            for (int r = 0; r < 2; r++) {
                const int px = pxb + mt*16 + g + r*8;
                float vx = acc[mt][nt][r*2]   * sc.x + bi.x;
                float vy = acc[mt][nt][r*2+1] * sc.y + bi.y;
                const size_t base = (size_t)(cam*NPIX + px)*256 + och*128 + ocl;
                if (MODE == 0) {
                    const float2 gt = *(float2*)&s_gt[ocl];
                    vx = fmaxf(vx, 0.f)*gt.x; vy = fmaxf(vy, 0.f)*gt.y;
                    *(float2*)&outf[base] = make_float2(vx, vy);
                } else if (MODE == 1) {
                    vx = fmaxf(vx, 0.f); vy = fmaxf(vy, 0.f);
                } else {
                    const float2 r0 = *(const float2*)&res[base];
                    vx = fmaxf(vx + r0.x, 0.f); vy = fmaxf(vy + r0.y, 0.f);
                    *(float2*)&outf[base] = make_float2(vx, vy);
                }
                if (MODE != 3) {
                    const __nv_bfloat16 h0 = __float2bfloat16(vx), h1 = __float2bfloat16(vy);
                    const uint32_t hp = (uint32_t)__bfloat16_as_ushort(h0)
                                      | ((uint32_t)__bfloat16_as_ushort(h1) << 16);
                    const uint32_t lp =
                          (uint32_t)__bfloat16_as_ushort(__float2bfloat16(vx - __bfloat162float(h0)))
                        | ((uint32_t)__bfloat16_as_ushort(__float2bfloat16(vy - __bfloat162float(h1))) << 16);
                    *(uint32_t*)&outh[base] = hp;
                    *(uint32_t*)&outl[base] = lp;
                }
            }
        }
}

// depth conv + softmax, weights cached in smem (112x257 padded), 8 px/block
#define DS_SMEM (112*257*4 + 8*256*4 + 64)
__global__ __launch_bounds__(128)
void depth_softmax_kernel(const float* __restrict__ x,
                          const float* __restrict__ w, const float* __restrict__ b,
                          float* __restrict__ dp)
{
    extern __shared__ float ds[];
    float* sw  = ds;               // [112][257]
    float* sx  = ds + 112*257;     // [8][256]
    float* red = sx + 8*256;       // [4]
    const int blk = blockIdx.x;
    const int cam = (blk*8) / NPIX, p0 = (blk*8) % NPIX;
    const int tid = threadIdx.x, lane = tid & 31, wrp = tid >> 5;

    for (int i = tid; i < 112*256; i += 128) {
        const int bin = i >> 8, c = i & 255;
        sw[bin*257 + c] = w[i];
    }
    const float* xc = x + ((size_t)cam*NPIX + p0) * 256;
    for (int i = tid; i < 512; i += 128)
        *(float4*)&sx[i*4] = *(const float4*)&xc[i*4];
    __syncthreads();

    const float bb = (tid < DBINS) ? b[tid] : 0.f;
    #pragma unroll 1
    for (int pp = 0; pp < 8; pp++) {
        float lg = -1e30f;
        if (tid < DBINS) {
            float a0 = 0.f, a1 = 0.f, a2 = 0.f, a3 = 0.f;
            const float* wr = sw + tid*257;
            const float* xr = sx + pp*256;
            #pragma unroll 8
            for (int c = 0; c < 256; c += 4) {
                a0 = fmaf(xr[c],   wr[c],   a0);
                a1 = fmaf(xr[c+1], wr[c+1], a1);
                a2 = fmaf(xr[c+2], wr[c+2], a2);
                a3 = fmaf(xr[c+3], wr[c+3], a3);
            }
            lg = (a0 + a1) + (a2 + a3) + bb;
        }
        float m = lg;
        #pragma unroll
        for (int o = 16; o; o >>= 1) m = fmaxf(m, __shfl_xor_sync(0xffffffffu, m, o));
        if (lane == 0) red[wrp] = m;
        __syncthreads();
        m = fmaxf(fmaxf(red[0], red[1]), fmaxf(red[2], red[3]));
        __syncthreads();
        const float e = (tid < DBINS) ? __expf(lg - m) : 0.f;
        float s = e;
        #pragma unroll
        for (int o = 16; o; o >>= 1) s += __shfl_xor_sync(0xffffffffu, s, o);
        if (lane == 0) red[wrp] = s;
        __syncthreads();
        s = red[0] + red[1] + red[2] + red[3];
        __syncthreads();
        if (tid < DBINS)
            dp[((size_t)cam*DBINS + tid)*NPIX + (p0 + pp)] = e / s;
    }
}

__global__ __launch_bounds__(256)
void sample_kernel(const float* __restrict__ grid, const float* __restrict__ dp,
                   float* __restrict__ out)
{
    const int v = blockIdx.x * blockDim.x + threadIdx.x;
    if (v >= NVOX) return;
    float agg = 0.f, mask = 0.f;
    #pragma unroll 1
    for (int cam = 0; cam < NCAM; cam++) {
        const float* g = grid + ((size_t)cam * NVOX + v) * 3;
        const float ix = ((g[0] + 1.f) * 88.f  - 1.f) * 0.5f;
        const float iy = ((g[1] + 1.f) * 32.f  - 1.f) * 0.5f;
        const float iz = ((g[2] + 1.f) * 112.f - 1.f) * 0.5f;
        const float fx0 = floorf(ix), fy0 = floorf(iy), fz0 = floorf(iz);
        const float fx = ix - fx0, fy = iy - fy0, fz = iz - fz0;
        const int x0 = (int)fx0, y0 = (int)fy0, z0 = (int)fz0;
        const float* dc = dp + (size_t)cam * DBINS * NPIX;
        #pragma unroll
        for (int dz = 0; dz < 2; dz++)
            #pragma unroll
            for (int dy = 0; dy < 2; dy++)
                #pragma unroll
                for (int dx = 0; dx < 2; dx++) {
                    const int xi = x0 + dx, yi = y0 + dy, zi = z0 + dz;
                    const float wv = (dx ? fx : 1.f-fx) * (dy ? fy : 1.f-fy) * (dz ? fz : 1.f-fz);
                    if (xi >= 0 && xi < WW && yi >= 0 && yi < HH && zi >= 0 && zi < DBINS) {
                        agg  += wv * dc[(size_t)zi*NPIX + yi*WW + xi];
                        mask += wv;
                    }
                }
    }
    out[v] = (mask > 0.f) ? (agg / mask) : agg;
}

extern "C" void kernel_launch(void* const* d_in, const int* in_sizes, int n_in,
                              void* d_out, int out_size)
{
    const float* img    = (const float*)d_in[0];
    const float* intr   = (const float*)d_in[1];
    const float* grid   = (const float*)d_in[2];
    const float* red_w  = (const float*)d_in[3];
    const float* red_s  = (const float*)d_in[4];
    const float* red_b  = (const float*)d_in[5];
    const float* mlp_w1 = (const float*)d_in[6];
    const float* mlp_b1 = (const float*)d_in[7];
    const float* mlp_w2 = (const float*)d_in[8];
    const float* mlp_b2 = (const float*)d_in[9];
    const float* se_rw  = (const float*)d_in[10];
    const float* se_rb  = (const float*)d_in[11];
    const float* se_ew  = (const float*)d_in[12];
    const float* se_eb  = (const float*)d_in[13];
    const float* bb_w   = (const float*)d_in[14];
    const float* bb_s   = (const float*)d_in[15];
    const float* bb_b   = (const float*)d_in[16];
    const float* dp_w   = (const float*)d_in[17];
    const float* dp_b   = (const float*)d_in[18];

    float *pxf, *pdp, *pg;
    __nv_bfloat16 *pih, *pil, *pxh, *pxl, *pyh, *pyl;
    cudaGetSymbolAddress((void**)&pxf, g_xf);
    cudaGetSymbolAddress((void**)&pdp, g_dp);
    cudaGetSymbolAddress((void**)&pg,  g_gate);
    cudaGetSymbolAddress((void**)&pih, g_imgh);
    cudaGetSymbolAddress((void**)&pil, g_imgl);
    cudaGetSymbolAddress((void**)&pxh, g_xh);
    cudaGetSymbolAddress((void**)&pxl, g_xl);
    cudaGetSymbolAddress((void**)&pyh, g_yh);
    cudaGetSymbolAddress((void**)&pyl, g_yl);

    cudaFuncSetAttribute(conv_kernel<512,0>, cudaFuncAttributeMaxDynamicSharedMemorySize, CONV_SMEM);
    cudaFuncSetAttribute(conv_kernel<256,1>, cudaFuncAttributeMaxDynamicSharedMemorySize, CONV_SMEM);
    cudaFuncSetAttribute(conv_kernel<256,2>, cudaFuncAttributeMaxDynamicSharedMemorySize, CONV_SMEM);
    cudaFuncSetAttribute(conv_kernel<256,3>, cudaFuncAttributeMaxDynamicSharedMemorySize, CONV_SMEM);
    cudaFuncSetAttribute(depth_softmax_kernel, cudaFuncAttributeMaxDynamicSharedMemorySize, DS_SMEM);

    gate_kernel<<<NCAM, 256>>>(intr, mlp_w1, mlp_b1, mlp_w2, mlp_b2,
                               se_rw, se_rb, se_ew, se_eb, pg);
    prep_img_kernel<<<dim3(22, 16, NCAM), 256>>>(img);
    wtrans_kernel<<<(WHT*128*64 + 255)/256, 256>>>(red_w, bb_w);

    dim3 cg(22, 2, NCAM);
    conv_kernel<512,0><<<cg, 512, CONV_SMEM>>>(pih, pil, 0, red_s, red_b, pg,
                                               nullptr, pxf, pxh, pxl);
    for (int i = 0; i < 3; i++) {
        conv_kernel<256,1><<<cg, 512, CONV_SMEM>>>(pxh, pxl, 144 + (2*i)*72,
            bb_s + (2*i)*MID, bb_b + (2*i)*MID, nullptr, nullptr, nullptr, pyh, pyl);
        if (i < 2)
            conv_kernel<256,2><<<cg, 512, CONV_SMEM>>>(pyh, pyl, 144 + (2*i+1)*72,
                bb_s + (2*i+1)*MID, bb_b + (2*i+1)*MID, nullptr, pxf, pxf, pxh, pxl);
        else
            conv_kernel<256,3><<<cg, 512, CONV_SMEM>>>(pyh, pyl, 144 + (2*i+1)*72,
                bb_s + (2*i+1)*MID, bb_b + (2*i+1)*MID, nullptr, pxf, pxf, pxh, pxl);
    }
    depth_softmax_kernel<<<NCAM * NPIX / 8, 128, DS_SMEM>>>(pxf, dp_w, dp_b, pdp);
    sample_kernel<<<(NVOX + 255)/256, 256>>>(grid, pdp, (float*)d_out);
}

// round 11
// speedup vs baseline: 1.1660x; 1.1205x over previous
#include <cuda_runtime.h>
#include <cuda_bf16.h>
#include <math.h>
#include <stdint.h>

#define NCAM 6
#define MID 256
#define DBINS 112
#define HH 32
#define WW 88
#define NPIX 2816
#define NVOX (128*128*16)
#define WHT 576

__device__ __align__(1024) float g_xf [NCAM*NPIX*MID];
__device__ __align__(1024) float g_dp [NCAM*DBINS*NPIX];
__device__ __align__(1024) float g_gate[NCAM*MID];
__device__ __align__(1024) __nv_bfloat16 g_imgh[NCAM*NPIX*512];
__device__ __align__(1024) __nv_bfloat16 g_imgl[NCAM*NPIX*512];
__device__ __align__(1024) __nv_bfloat16 g_xh[NCAM*NPIX*MID];
__device__ __align__(1024) __nv_bfloat16 g_xl[NCAM*NPIX*MID];
__device__ __align__(1024) __nv_bfloat16 g_yh[NCAM*NPIX*MID];
__device__ __align__(1024) __nv_bfloat16 g_yl[NCAM*NPIX*MID];
__device__ __align__(1024) __nv_bfloat16 g_Wh[WHT*128*64];
__device__ __align__(1024) __nv_bfloat16 g_Wl[WHT*128*64];

__device__ __forceinline__ uint32_t smem_u32(const void* p) {
    uint32_t a;
    asm("{ .reg .u64 t; cvta.to.shared.u64 t, %1; cvt.u32.u64 %0, t; }" : "=r"(a) : "l"(p));
    return a;
}
#define SW128(o) ((o) ^ (((o) >> 3) & 0x70))
#define LDM4(r0,r1,r2,r3,addr) \
    asm volatile("ldmatrix.sync.aligned.m8n8.x4.shared.b16 {%0,%1,%2,%3}, [%4];" \
        : "=r"(r0),"=r"(r1),"=r"(r2),"=r"(r3) : "r"(addr))
#define MMA(d,a,b0,b1) \
    asm volatile("mma.sync.aligned.m16n8k16.row.col.f32.bf16.bf16.f32 " \
        "{%0,%1,%2,%3},{%4,%5,%6,%7},{%8,%9},{%0,%1,%2,%3};" \
        : "+f"((d)[0]),"+f"((d)[1]),"+f"((d)[2]),"+f"((d)[3]) \
        : "r"((a)[0]),"r"((a)[1]),"r"((a)[2]),"r"((a)[3]),"r"(b0),"r"(b1))
__device__ __forceinline__ void cpa16(uint32_t dst, const void* src, int sz) {
    asm volatile("cp.async.cg.shared.global [%0], [%1], 16, %2;" :: "r"(dst), "l"(src), "r"(sz) : "memory");
}
#define CPA_COMMIT() asm volatile("cp.async.commit_group;" ::: "memory")

__global__ __launch_bounds__(256) void prep_img_kernel(const float* __restrict__ img)
{
    __shared__ float st[32][128];
    const int px0 = blockIdx.x * 128, cg = blockIdx.y, cam = blockIdx.z;
    const int tid = threadIdx.x;
    for (int i = tid; i < 32*128; i += 256) {
        const int c = i >> 7, p = i & 127;
        st[c][p] = img[((size_t)cam*512 + cg*32 + c)*NPIX + px0 + p];
    }
    __syncthreads();
    for (int i = tid; i < 128*32; i += 256) {
        const int p = i >> 5, c = i & 31;
        float v = st[c][p];
        __nv_bfloat16 h = __float2bfloat16(v);
        __nv_bfloat16 l = __float2bfloat16(v - __bfloat162float(h));
        const size_t o = ((size_t)(cam*NPIX + px0 + p))*512 + cg*32 + c;
        g_imgh[o] = h; g_imgl[o] = l;
    }
}

__global__ __launch_bounds__(256) void wtrans_kernel(const float* __restrict__ red_w,
                                                     const float* __restrict__ bb_w)
{
    const int idx = blockIdx.x*256 + threadIdx.x;
    if (idx >= WHT*128*64) return;
    const int r = idx >> 6, ci = idx & 63;
    const int ht = r >> 7, ocl = r & 127;
    float w;
    if (ht < 144) {
        const int g = ht >> 1, half = ht & 1, tap = g >> 3, cig = g & 7;
        w = red_w[((size_t)(half*128 + ocl)*512 + cig*64 + ci)*9 + tap];
    } else {
        const int h2 = ht - 144, layer = h2 / 72, rr = h2 % 72;
        const int g = rr >> 1, half = rr & 1, tap = g >> 2, cig = g & 3;
        w = bb_w[(size_t)layer*589824 + ((size_t)(half*128 + ocl)*256 + cig*64 + ci)*9 + tap];
    }
    __nv_bfloat16 h = __float2bfloat16(w);
    __nv_bfloat16 l = __float2bfloat16(w - __bfloat162float(h));
    const size_t off = (size_t)ht*16384 + SW128((uint32_t)(ocl*128 + ci*2));
    *(uint16_t*)((char*)g_Wh + off) = __bfloat16_as_ushort(h);
    *(uint16_t*)((char*)g_Wl + off) = __bfloat16_as_ushort(l);
}

__global__ void gate_kernel(const float* __restrict__ intr,
                            const float* __restrict__ w1, const float* __restrict__ b1,
                            const float* __restrict__ w2, const float* __restrict__ b2,
                            const float* __restrict__ rw, const float* __restrict__ rb,
                            const float* __restrict__ ew, const float* __restrict__ eb,
                            float* __restrict__ gate)
{
    int cam = blockIdx.x, tid = threadIdx.x;
    __shared__ float sp_s, h[256], h2[256], t[256];
    if (tid == 0) {
        double A[4][8];
        for (int r = 0; r < 4; r++) {
            for (int c = 0; c < 4; c++) A[r][c] = (double)intr[cam*16 + r*4 + c];
            for (int c = 0; c < 4; c++) A[r][4+c] = (r == c) ? 1.0 : 0.0;
        }
        for (int col = 0; col < 4; col++) {
            int piv = col; double best = fabs(A[col][col]);
            for (int r = col+1; r < 4; r++)
                if (fabs(A[r][col]) > best) { best = fabs(A[r][col]); piv = r; }
            if (piv != col)
                for (int c = 0; c < 8; c++) { double tmp = A[col][c]; A[col][c] = A[piv][c]; A[piv][c] = tmp; }
            double d = A[col][col];
            for (int c = 0; c < 8; c++) A[col][c] /= d;
            for (int r = 0; r < 4; r++) if (r != col) {
                double f = A[r][col];
                for (int c = 0; c < 8; c++) A[r][c] -= f * A[col][c];
            }
        }
        sp_s = (float)(1000.0 * sqrt(A[0][4]*A[0][4] + A[1][5]*A[1][5]));
    }
    __syncthreads();
    float sp = sp_s;
    h[tid] = fmaxf(sp * w1[tid] + b1[tid], 0.f);
    __syncthreads();
    float s = b2[tid];
    for (int k = 0; k < 256; k++) s += h[k] * w2[k*256 + tid];
    h2[tid] = s;
    __syncthreads();
    s = rb[tid];
    for (int c = 0; c < 256; c++) s += rw[tid*256 + c] * h2[c];
    t[tid] = fmaxf(s, 0.f);
    __syncthreads();
    s = eb[tid];
    for (int c = 0; c < 256; c++) s += ew[tid*256 + c] * t[c];
    gate[cam*256 + tid] = 1.f / (1.f + __expf(-s));
}

// HMMA conv: block tile 128px x 256oc, 16 warps (4x4), warp tile 32x64.
// 2-stage cp.async, single sync per chunk. Grid (22,1,6).
// Buffer: A hi 16K | A lo 16K | B hi 32K | B lo 32K = 96KB
#define BUF 98304
#define CONV_SMEM (4096 + 2*BUF)
template<int CIN, int MODE>
__global__ void __launch_bounds__(512, 1)
conv_kernel(const __nv_bfloat16* __restrict__ inh, const __nv_bfloat16* __restrict__ inl,
            int aoff,
            const float* __restrict__ scale, const float* __restrict__ bias,
            const float* __restrict__ gate,  const float* res,
            float* outf, __nv_bfloat16* __restrict__ outh, __nv_bfloat16* __restrict__ outl)
{
    constexpr int CIG = CIN / 64, NCH = 9 * CIG;
    extern __shared__ __align__(1024) char smem[];
    float* s_sc = (float*)smem;
    float* s_bi = (float*)(smem + 1024);
    float* s_gt = (float*)(smem + 2048);
    const uint32_t sb0 = smem_u32(smem) + 4096;

    const int pxt = blockIdx.x, cam = blockIdx.z;
    const int tid = threadIdx.x, wid = tid >> 5, lane = tid & 31;
    const int wm = wid & 3, wn = wid >> 2;          // 4 px-warps x 4 oc-warps
    const int g = lane >> 2, tig = lane & 3;

    if (tid < 256) {
        s_sc[tid] = scale[tid];
        s_bi[tid] = bias [tid];
        s_gt[tid] = (MODE == 0) ? gate[cam*256 + tid] : 0.f;
    }

    float acc[2][8][4];
    #pragma unroll
    for (int a = 0; a < 2; a++)
        #pragma unroll
        for (int b = 0; b < 8; b++)
            #pragma unroll
            for (int c = 0; c < 4; c++) acc[a][b][c] = 0.f;

    const int arow = wm*32 + (lane & 15);
    const int ak16 = (lane >> 4) << 4;
    const int brow = wn*64 + (lane & 7) + ((lane >> 4) << 3);
    const int bk16 = ((lane >> 3) & 1) << 4;

    auto stage = [&](int j, int b) {
        const uint32_t dA = sb0 + b*BUF, dB = dA + 32768;
        // B: two pre-swizzled 16KB half-tiles, contiguous (rows 0-127, 128-255)
        const char* sH = (const char*)g_Wh + (size_t)(aoff + j*2) * 16384;
        const char* sL = (const char*)g_Wl + (size_t)(aoff + j*2) * 16384;
        #pragma unroll
        for (int t = 0; t < 4; t++) {
            const uint32_t o = (tid + 512*t) * 16;   // 0..32767
            cpa16(dB + o,         sH + o, 16);
            cpa16(dB + 32768 + o, sL + o, 16);
        }
        // A: im2col gather 128px x 64ci
        const int tap = j / CIG, cig = j - tap*CIG;
        const int dh = tap/3 - 1, dw = tap%3 - 1;
        #pragma unroll
        for (int t = 0; t < 2; t++) {
            const int u = tid + 512*t;
            const int px = u >> 3, q = u & 7;
            const int p = pxt*128 + px;
            const int h = p/88 + dh, w = p - (p/88)*88 + dw;
            const bool ok = ((unsigned)h < 32u) & ((unsigned)w < 88u);
            const size_t s0 = ok ? (((size_t)(cam*NPIX + h*88 + w))*CIN + cig*64 + q*8) : 0;
            const int sz = ok ? 16 : 0;
            const uint32_t sw = SW128((uint32_t)(px*128 + q*16));
            cpa16(dA + sw,         inh + s0, sz);
            cpa16(dA + 16384 + sw, inl + s0, sz);
        }
        CPA_COMMIT();
    };

    stage(0, 0);
    #pragma unroll 1
    for (int j = 0; j < NCH; j++) {
        const int b = j & 1;
        asm volatile("cp.async.wait_group 0;" ::: "memory");
        __syncthreads();
        if (j + 1 < NCH) stage(j + 1, 1 - b);

        const uint32_t sbA = sb0 + b*BUF, sbB = sbA + 32768;
        #pragma unroll
        for (int ks = 0; ks < 4; ks++) {
            uint32_t ah[2][4], al[2][4];
            #pragma unroll
            for (int mt = 0; mt < 2; mt++) {
                const uint32_t off = (uint32_t)((arow + mt*16)*128 + ks*32) + ak16;
                LDM4(ah[mt][0],ah[mt][1],ah[mt][2],ah[mt][3], sbA + SW128(off));
                LDM4(al[mt][0],al[mt][1],al[mt][2],al[mt][3], sbA + 16384 + SW128(off));
            }
            #pragma unroll
            for (int np = 0; np < 4; np++) {
                uint32_t bh[4], bl[4];
                const uint32_t boff = (uint32_t)((brow + np*16)*128 + ks*32) + bk16;
                LDM4(bh[0],bh[1],bh[2],bh[3], sbB + SW128(boff));
                LDM4(bl[0],bl[1],bl[2],bl[3], sbB + 32768 + SW128(boff));
                #pragma unroll
                for (int mt = 0; mt < 2; mt++) {
                    MMA(acc[mt][np*2],   ah[mt], bh[0], bh[1]);
                    MMA(acc[mt][np*2+1], ah[mt], bh[2], bh[3]);
                    MMA(acc[mt][np*2],   ah[mt], bl[0], bl[1]);
                    MMA(acc[mt][np*2+1], ah[mt], bl[2], bl[3]);
                    MMA(acc[mt][np*2],   al[mt], bh[0], bh[1]);
                    MMA(acc[mt][np*2+1], al[mt], bh[2], bh[3]);
                }
            }
        }
    }

    const int pxb = pxt*128 + wm*32;
    #pragma unroll
    for (int mt = 0; mt < 2; mt++)
        #pragma unroll
        for (int nt = 0; nt < 8; nt++) {
            const int ocl = wn*64 + nt*8 + 2*tig;
            const float2 sc = *(float2*)&s_sc[ocl];
            const float2 bi = *(float2*)&s_bi[ocl];
            #pragma unroll
            for (int r = 0; r < 2; r++) {
                const int px = pxb + mt*16 + g + r*8;
                float vx = acc[mt][nt][r*2]   * sc.x + bi.x;
                float vy = acc[mt][nt][r*2+1] * sc.y + bi.y;
                const size_t base = (size_t)(cam*NPIX + px)*256 + ocl;
                if (MODE == 0) {
                    const float2 gt = *(float2*)&s_gt[ocl];
                    vx = fmaxf(vx, 0.f)*gt.x; vy = fmaxf(vy, 0.f)*gt.y;
                    *(float2*)&outf[base] = make_float2(vx, vy);
                } else if (MODE == 1) {
                    vx = fmaxf(vx, 0.f); vy = fmaxf(vy, 0.f);
                } else {
                    const float2 r0 = *(const float2*)&res[base];
                    vx = fmaxf(vx + r0.x, 0.f); vy = fmaxf(vy + r0.y, 0.f);
                    *(float2*)&outf[base] = make_float2(vx, vy);
                }
                if (MODE != 3) {
                    const __nv_bfloat16 h0 = __float2bfloat16(vx), h1 = __float2bfloat16(vy);
                    const uint32_t hp = (uint32_t)__bfloat16_as_ushort(h0)
                                      | ((uint32_t)__bfloat16_as_ushort(h1) << 16);
                    const uint32_t lp =
                          (uint32_t)__bfloat16_as_ushort(__float2bfloat16(vx - __bfloat162float(h0)))
                        | ((uint32_t)__bfloat16_as_ushort(__float2bfloat16(vy - __bfloat162float(h1))) << 16);
                    *(uint32_t*)&outh[base] = hp;
                    *(uint32_t*)&outl[base] = lp;
                }
            }
        }
}

// depth conv + softmax, weights cached in smem (112x257 padded), 8 px/block
#define DS_SMEM (112*257*4 + 8*256*4 + 64)
__global__ __launch_bounds__(128)
void depth_softmax_kernel(const float* __restrict__ x,
                          const float* __restrict__ w, const float* __restrict__ b,
                          float* __restrict__ dp)
{
    extern __shared__ float ds[];
    float* sw  = ds;
    float* sx  = ds + 112*257;
    float* red = sx + 8*256;
    const int blk = blockIdx.x;
    const int cam = (blk*8) / NPIX, p0 = (blk*8) % NPIX;
    const int tid = threadIdx.x, lane = tid & 31, wrp = tid >> 5;

    for (int i = tid; i < 112*256; i += 128) {
        const int bin = i >> 8, c = i & 255;
        sw[bin*257 + c] = w[i];
    }
    const float* xc = x + ((size_t)cam*NPIX + p0) * 256;
    for (int i = tid; i < 512; i += 128)
        *(float4*)&sx[i*4] = *(const float4*)&xc[i*4];
    __syncthreads();

    const float bb = (tid < DBINS) ? b[tid] : 0.f;
    #pragma unroll 1
    for (int pp = 0; pp < 8; pp++) {
        float lg = -1e30f;
        if (tid < DBINS) {
            float a0 = 0.f, a1 = 0.f, a2 = 0.f, a3 = 0.f;
            const float* wr = sw + tid*257;
            const float* xr = sx + pp*256;
            #pragma unroll 8
            for (int c = 0; c < 256; c += 4) {
                a0 = fmaf(xr[c],   wr[c],   a0);
                a1 = fmaf(xr[c+1], wr[c+1], a1);
                a2 = fmaf(xr[c+2], wr[c+2], a2);
                a3 = fmaf(xr[c+3], wr[c+3], a3);
            }
            lg = (a0 + a1) + (a2 + a3) + bb;
        }
        float m = lg;
        #pragma unroll
        for (int o = 16; o; o >>= 1) m = fmaxf(m, __shfl_xor_sync(0xffffffffu, m, o));
        if (lane == 0) red[wrp] = m;
        __syncthreads();
        m = fmaxf(fmaxf(red[0], red[1]), fmaxf(red[2], red[3]));
        __syncthreads();
        const float e = (tid < DBINS) ? __expf(lg - m) : 0.f;
        float s = e;
        #pragma unroll
        for (int o = 16; o; o >>= 1) s += __shfl_xor_sync(0xffffffffu, s, o);
        if (lane == 0) red[wrp] = s;
        __syncthreads();
        s = red[0] + red[1] + red[2] + red[3];
        __syncthreads();
        if (tid < DBINS)
            dp[((size_t)cam*DBINS + tid)*NPIX + (p0 + pp)] = e / s;
    }
}

__global__ __launch_bounds__(256)
void sample_kernel(const float* __restrict__ grid, const float* __restrict__ dp,
                   float* __restrict__ out)
{
    const int v = blockIdx.x * blockDim.x + threadIdx.x;
    if (v >= NVOX) return;
    float agg = 0.f, mask = 0.f;
    #pragma unroll 1
    for (int cam = 0; cam < NCAM; cam++) {
        const float* g = grid + ((size_t)cam * NVOX + v) * 3;
        const float ix = ((g[0] + 1.f) * 88.f  - 1.f) * 0.5f;
        const float iy = ((g[1] + 1.f) * 32.f  - 1.f) * 0.5f;
        const float iz = ((g[2] + 1.f) * 112.f - 1.f) * 0.5f;
        const float fx0 = floorf(ix), fy0 = floorf(iy), fz0 = floorf(iz);
        const float fx = ix - fx0, fy = iy - fy0, fz = iz - fz0;
        const int x0 = (int)fx0, y0 = (int)fy0, z0 = (int)fz0;
        const float* dc = dp + (size_t)cam * DBINS * NPIX;
        #pragma unroll
        for (int dz = 0; dz < 2; dz++)
            #pragma unroll
            for (int dy = 0; dy < 2; dy++)
                #pragma unroll
                for (int dx = 0; dx < 2; dx++) {
                    const int xi = x0 + dx, yi = y0 + dy, zi = z0 + dz;
                    const float wv = (dx ? fx : 1.f-fx) * (dy ? fy : 1.f-fy) * (dz ? fz : 1.f-fz);
                    if (xi >= 0 && xi < WW && yi >= 0 && yi < HH && zi >= 0 && zi < DBINS) {
                        agg  += wv * dc[(size_t)zi*NPIX + yi*WW + xi];
                        mask += wv;
                    }
                }
    }
    out[v] = (mask > 0.f) ? (agg / mask) : agg;
}

extern "C" void kernel_launch(void* const* d_in, const int* in_sizes, int n_in,
                              void* d_out, int out_size)
{
    const float* img    = (const float*)d_in[0];
    const float* intr   = (const float*)d_in[1];
    const float* grid   = (const float*)d_in[2];
    const float* red_w  = (const float*)d_in[3];
    const float* red_s  = (const float*)d_in[4];
    const float* red_b  = (const float*)d_in[5];
    const float* mlp_w1 = (const float*)d_in[6];
    const float* mlp_b1 = (const float*)d_in[7];
    const float* mlp_w2 = (const float*)d_in[8];
    const float* mlp_b2 = (const float*)d_in[9];
    const float* se_rw  = (const float*)d_in[10];
    const float* se_rb  = (const float*)d_in[11];
    const float* se_ew  = (const float*)d_in[12];
    const float* se_eb  = (const float*)d_in[13];
    const float* bb_w   = (const float*)d_in[14];
    const float* bb_s   = (const float*)d_in[15];
    const float* bb_b   = (const float*)d_in[16];
    const float* dp_w   = (const float*)d_in[17];
    const float* dp_b   = (const float*)d_in[18];

    float *pxf, *pdp, *pg;
    __nv_bfloat16 *pih, *pil, *pxh, *pxl, *pyh, *pyl;
    cudaGetSymbolAddress((void**)&pxf, g_xf);
    cudaGetSymbolAddress((void**)&pdp, g_dp);
    cudaGetSymbolAddress((void**)&pg,  g_gate);
    cudaGetSymbolAddress((void**)&pih, g_imgh);
    cudaGetSymbolAddress((void**)&pil, g_imgl);
    cudaGetSymbolAddress((void**)&pxh, g_xh);
    cudaGetSymbolAddress((void**)&pxl, g_xl);
    cudaGetSymbolAddress((void**)&pyh, g_yh);
    cudaGetSymbolAddress((void**)&pyl, g_yl);

    cudaFuncSetAttribute(conv_kernel<512,0>, cudaFuncAttributeMaxDynamicSharedMemorySize, CONV_SMEM);
    cudaFuncSetAttribute(conv_kernel<256,1>, cudaFuncAttributeMaxDynamicSharedMemorySize, CONV_SMEM);
    cudaFuncSetAttribute(conv_kernel<256,2>, cudaFuncAttributeMaxDynamicSharedMemorySize, CONV_SMEM);
    cudaFuncSetAttribute(conv_kernel<256,3>, cudaFuncAttributeMaxDynamicSharedMemorySize, CONV_SMEM);
    cudaFuncSetAttribute(depth_softmax_kernel, cudaFuncAttributeMaxDynamicSharedMemorySize, DS_SMEM);

    gate_kernel<<<NCAM, 256>>>(intr, mlp_w1, mlp_b1, mlp_w2, mlp_b2,
                               se_rw, se_rb, se_ew, se_eb, pg);
    prep_img_kernel<<<dim3(22, 16, NCAM), 256>>>(img);
    wtrans_kernel<<<(WHT*128*64 + 255)/256, 256>>>(red_w, bb_w);

    dim3 cg(22, 1, NCAM);
    conv_kernel<512,0><<<cg, 512, CONV_SMEM>>>(pih, pil, 0, red_s, red_b, pg,
                                               nullptr, pxf, pxh, pxl);
    for (int i = 0; i < 3; i++) {
        conv_kernel<256,1><<<cg, 512, CONV_SMEM>>>(pxh, pxl, 144 + (2*i)*72,
            bb_s + (2*i)*MID, bb_b + (2*i)*MID, nullptr, nullptr, nullptr, pyh, pyl);
        if (i < 2)
            conv_kernel<256,2><<<cg, 512, CONV_SMEM>>>(pyh, pyl, 144 + (2*i+1)*72,
                bb_s + (2*i+1)*MID, bb_b + (2*i+1)*MID, nullptr, pxf, pxf, pxh, pxl);
        else
            conv_kernel<256,3><<<cg, 512, CONV_SMEM>>>(pyh, pyl, 144 + (2*i+1)*72,
                bb_s + (2*i+1)*MID, bb_b + (2*i+1)*MID, nullptr, pxf, pxf, pxh, pxl);
    }
    depth_softmax_kernel<<<NCAM * NPIX / 8, 128, DS_SMEM>>>(pxf, dp_w, dp_b, pdp);
    sample_kernel<<<(NVOX + 255)/256, 256>>>(grid, pdp, (float*)d_out);
}

// round 12
// speedup vs baseline: 1.2302x; 1.0551x over previous
#include <cuda_runtime.h>
#include <cuda_bf16.h>
#include <math.h>
#include <stdint.h>

#define NCAM 6
#define MID 256
#define DBINS 112
#define HH 32
#define WW 88
#define NPIX 2816
#define NVOX (128*128*16)
#define WHT 576

__device__ __align__(1024) float g_xf [NCAM*NPIX*MID];
__device__ __align__(1024) float g_dp [NCAM*NPIX*DBINS];   // [cam][pix][bin]
__device__ __align__(1024) float g_gate[NCAM*MID];
__device__ __align__(1024) __nv_bfloat16 g_imgh[NCAM*NPIX*512];
__device__ __align__(1024) __nv_bfloat16 g_imgl[NCAM*NPIX*512];
__device__ __align__(1024) __nv_bfloat16 g_xh[NCAM*NPIX*MID];
__device__ __align__(1024) __nv_bfloat16 g_xl[NCAM*NPIX*MID];
__device__ __align__(1024) __nv_bfloat16 g_yh[NCAM*NPIX*MID];
__device__ __align__(1024) __nv_bfloat16 g_yl[NCAM*NPIX*MID];
__device__ __align__(1024) __nv_bfloat16 g_Wh[WHT*128*64];
__device__ __align__(1024) __nv_bfloat16 g_Wl[WHT*128*64];

__device__ __forceinline__ uint32_t smem_u32(const void* p) {
    uint32_t a;
    asm("{ .reg .u64 t; cvta.to.shared.u64 t, %1; cvt.u32.u64 %0, t; }" : "=r"(a) : "l"(p));
    return a;
}
#define SW128(o) ((o) ^ (((o) >> 3) & 0x70))
#define LDM4(r0,r1,r2,r3,addr) \
    asm volatile("ldmatrix.sync.aligned.m8n8.x4.shared.b16 {%0,%1,%2,%3}, [%4];" \
        : "=r"(r0),"=r"(r1),"=r"(r2),"=r"(r3) : "r"(addr))
#define MMA(d,a,b0,b1) \
    asm volatile("mma.sync.aligned.m16n8k16.row.col.f32.bf16.bf16.f32 " \
        "{%0,%1,%2,%3},{%4,%5,%6,%7},{%8,%9},{%0,%1,%2,%3};" \
        : "+f"((d)[0]),"+f"((d)[1]),"+f"((d)[2]),"+f"((d)[3]) \
        : "r"((a)[0]),"r"((a)[1]),"r"((a)[2]),"r"((a)[3]),"r"(b0),"r"(b1))
__device__ __forceinline__ void cpa16(uint32_t dst, const void* src, int sz) {
    asm volatile("cp.async.cg.shared.global [%0], [%1], 16, %2;" :: "r"(dst), "l"(src), "r"(sz) : "memory");
}
#define CPA_COMMIT() asm volatile("cp.async.commit_group;" ::: "memory")

// img [cam][512][px] f32 -> [cam][px][512] bf16 hi/lo, coalesced uint2 writes
__global__ __launch_bounds__(256) void prep_img_kernel(const float* __restrict__ img)
{
    __shared__ float st[64][129];
    const int px0 = blockIdx.x * 128, cg = blockIdx.y, cam = blockIdx.z;  // cg 0..7
    const int tid = threadIdx.x;
    for (int i = tid; i < 64*128; i += 256) {
        const int c = i >> 7, p = i & 127;
        st[c][p] = img[((size_t)cam*512 + cg*64 + c)*NPIX + px0 + p];
    }
    __syncthreads();
    for (int i = tid; i < 128*16; i += 256) {
        const int p = i >> 4, c4 = (i & 15) * 4;
        const float v0 = st[c4][p], v1 = st[c4+1][p], v2 = st[c4+2][p], v3 = st[c4+3][p];
        const __nv_bfloat16 h0 = __float2bfloat16(v0), h1 = __float2bfloat16(v1);
        const __nv_bfloat16 h2 = __float2bfloat16(v2), h3 = __float2bfloat16(v3);
        uint2 hp, lp;
        hp.x = (uint32_t)__bfloat16_as_ushort(h0) | ((uint32_t)__bfloat16_as_ushort(h1) << 16);
        hp.y = (uint32_t)__bfloat16_as_ushort(h2) | ((uint32_t)__bfloat16_as_ushort(h3) << 16);
        lp.x = (uint32_t)__bfloat16_as_ushort(__float2bfloat16(v0 - __bfloat162float(h0)))
             | ((uint32_t)__bfloat16_as_ushort(__float2bfloat16(v1 - __bfloat162float(h1))) << 16);
        lp.y = (uint32_t)__bfloat16_as_ushort(__float2bfloat16(v2 - __bfloat162float(h2)))
             | ((uint32_t)__bfloat16_as_ushort(__float2bfloat16(v3 - __bfloat162float(h3))) << 16);
        const size_t o = ((size_t)(cam*NPIX + px0 + p))*512 + cg*64 + c4;
        *(uint2*)&g_imgh[o] = hp;
        *(uint2*)&g_imgl[o] = lp;
    }
}

__global__ __launch_bounds__(256) void wtrans_kernel(const float* __restrict__ red_w,
                                                     const float* __restrict__ bb_w)
{
    const int idx = blockIdx.x*256 + threadIdx.x;
    if (idx >= WHT*128*64) return;
    const int r = idx >> 6, ci = idx & 63;
    const int ht = r >> 7, ocl = r & 127;
    float w;
    if (ht < 144) {
        const int g = ht >> 1, half = ht & 1, tap = g >> 3, cig = g & 7;
        w = red_w[((size_t)(half*128 + ocl)*512 + cig*64 + ci)*9 + tap];
    } else {
        const int h2 = ht - 144, layer = h2 / 72, rr = h2 % 72;
        const int g = rr >> 1, half = rr & 1, tap = g >> 2, cig = g & 3;
        w = bb_w[(size_t)layer*589824 + ((size_t)(half*128 + ocl)*256 + cig*64 + ci)*9 + tap];
    }
    __nv_bfloat16 h = __float2bfloat16(w);
    __nv_bfloat16 l = __float2bfloat16(w - __bfloat162float(h));
    const size_t off = (size_t)ht*16384 + SW128((uint32_t)(ocl*128 + ci*2));
    *(uint16_t*)((char*)g_Wh + off) = __bfloat16_as_ushort(h);
    *(uint16_t*)((char*)g_Wl + off) = __bfloat16_as_ushort(l);
}

__global__ void gate_kernel(const float* __restrict__ intr,
                            const float* __restrict__ w1, const float* __restrict__ b1,
                            const float* __restrict__ w2, const float* __restrict__ b2,
                            const float* __restrict__ rw, const float* __restrict__ rb,
                            const float* __restrict__ ew, const float* __restrict__ eb,
                            float* __restrict__ gate)
{
    int cam = blockIdx.x, tid = threadIdx.x;
    __shared__ float sp_s, h[256], h2[256], t[256];
    if (tid == 0) {
        double A[4][8];
        for (int r = 0; r < 4; r++) {
            for (int c = 0; c < 4; c++) A[r][c] = (double)intr[cam*16 + r*4 + c];
            for (int c = 0; c < 4; c++) A[r][4+c] = (r == c) ? 1.0 : 0.0;
        }
        for (int col = 0; col < 4; col++) {
            int piv = col; double best = fabs(A[col][col]);
            for (int r = col+1; r < 4; r++)
                if (fabs(A[r][col]) > best) { best = fabs(A[r][col]); piv = r; }
            if (piv != col)
                for (int c = 0; c < 8; c++) { double tmp = A[col][c]; A[col][c] = A[piv][c]; A[piv][c] = tmp; }
            double d = A[col][col];
            for (int c = 0; c < 8; c++) A[col][c] /= d;
            for (int r = 0; r < 4; r++) if (r != col) {
                double f = A[r][col];
                for (int c = 0; c < 8; c++) A[r][c] -= f * A[col][c];
            }
        }
        sp_s = (float)(1000.0 * sqrt(A[0][4]*A[0][4] + A[1][5]*A[1][5]));
    }
    __syncthreads();
    float sp = sp_s;
    h[tid] = fmaxf(sp * w1[tid] + b1[tid], 0.f);
    __syncthreads();
    float s = b2[tid];
    for (int k = 0; k < 256; k++) s += h[k] * w2[k*256 + tid];
    h2[tid] = s;
    __syncthreads();
    s = rb[tid];
    for (int c = 0; c < 256; c++) s += rw[tid*256 + c] * h2[c];
    t[tid] = fmaxf(s, 0.f);
    __syncthreads();
    s = eb[tid];
    for (int c = 0; c < 256; c++) s += ew[tid*256 + c] * t[c];
    gate[cam*256 + tid] = 1.f / (1.f + __expf(-s));
}

// HMMA conv: block tile 128px x 256oc, 16 warps (4x4), warp tile 32x64. Grid (22,1,6).
#define BUF 98304
#define CONV_SMEM (4096 + 2*BUF)
template<int CIN, int MODE>
__global__ void __launch_bounds__(512, 1)
conv_kernel(const __nv_bfloat16* __restrict__ inh, const __nv_bfloat16* __restrict__ inl,
            int aoff,
            const float* __restrict__ scale, const float* __restrict__ bias,
            const float* __restrict__ gate,  const float* res,
            float* outf, __nv_bfloat16* __restrict__ outh, __nv_bfloat16* __restrict__ outl)
{
    constexpr int CIG = CIN / 64, NCH = 9 * CIG;
    extern __shared__ __align__(1024) char smem[];
    float* s_sc = (float*)smem;
    float* s_bi = (float*)(smem + 1024);
    float* s_gt = (float*)(smem + 2048);
    const uint32_t sb0 = smem_u32(smem) + 4096;

    const int pxt = blockIdx.x, cam = blockIdx.z;
    const int tid = threadIdx.x, wid = tid >> 5, lane = tid & 31;
    const int wm = wid & 3, wn = wid >> 2;
    const int g = lane >> 2, tig = lane & 3;

    if (tid < 256) {
        s_sc[tid] = scale[tid];
        s_bi[tid] = bias [tid];
        s_gt[tid] = (MODE == 0) ? gate[cam*256 + tid] : 0.f;
    }

    float acc[2][8][4];
    #pragma unroll
    for (int a = 0; a < 2; a++)
        #pragma unroll
        for (int b = 0; b < 8; b++)
            #pragma unroll
            for (int c = 0; c < 4; c++) acc[a][b][c] = 0.f;

    const int arow = wm*32 + (lane & 15);
    const int ak16 = (lane >> 4) << 4;
    const int brow = wn*64 + (lane & 7) + ((lane >> 4) << 3);
    const int bk16 = ((lane >> 3) & 1) << 4;

    auto stage = [&](int j, int b) {
        const uint32_t dA = sb0 + b*BUF, dB = dA + 32768;
        const char* sH = (const char*)g_Wh + (size_t)(aoff + j*2) * 16384;
        const char* sL = (const char*)g_Wl + (size_t)(aoff + j*2) * 16384;
        #pragma unroll
        for (int t = 0; t < 4; t++) {
            const uint32_t o = (tid + 512*t) * 16;
            cpa16(dB + o,         sH + o, 16);
            cpa16(dB + 32768 + o, sL + o, 16);
        }
        const int tap = j / CIG, cig = j - tap*CIG;
        const int dh = tap/3 - 1, dw = tap%3 - 1;
        #pragma unroll
        for (int t = 0; t < 2; t++) {
            const int u = tid + 512*t;
            const int px = u >> 3, q = u & 7;
            const int p = pxt*128 + px;
            const int h = p/88 + dh, w = p - (p/88)*88 + dw;
            const bool ok = ((unsigned)h < 32u) & ((unsigned)w < 88u);
            const size_t s0 = ok ? (((size_t)(cam*NPIX + h*88 + w))*CIN + cig*64 + q*8) : 0;
            const int sz = ok ? 16 : 0;
            const uint32_t sw = SW128((uint32_t)(px*128 + q*16));
            cpa16(dA + sw,         inh + s0, sz);
            cpa16(dA + 16384 + sw, inl + s0, sz);
        }
        CPA_COMMIT();
    };

    stage(0, 0);
    #pragma unroll 1
    for (int j = 0; j < NCH; j++) {
        const int b = j & 1;
        asm volatile("cp.async.wait_group 0;" ::: "memory");
        __syncthreads();
        if (j + 1 < NCH) stage(j + 1, 1 - b);

        const uint32_t sbA = sb0 + b*BUF, sbB = sbA + 32768;
        #pragma unroll
        for (int ks = 0; ks < 4; ks++) {
            uint32_t ah[2][4], al[2][4];
            #pragma unroll
            for (int mt = 0; mt < 2; mt++) {
                const uint32_t off = (uint32_t)((arow + mt*16)*128 + ks*32) + ak16;
                LDM4(ah[mt][0],ah[mt][1],ah[mt][2],ah[mt][3], sbA + SW128(off));
                LDM4(al[mt][0],al[mt][1],al[mt][2],al[mt][3], sbA + 16384 + SW128(off));
            }
            #pragma unroll
            for (int np = 0; np < 4; np++) {
                uint32_t bh[4], bl[4];
                const uint32_t boff = (uint32_t)((brow + np*16)*128 + ks*32) + bk16;
                LDM4(bh[0],bh[1],bh[2],bh[3], sbB + SW128(boff));
                LDM4(bl[0],bl[1],bl[2],bl[3], sbB + 32768 + SW128(boff));
                #pragma unroll
                for (int mt = 0; mt < 2; mt++) {
                    MMA(acc[mt][np*2],   ah[mt], bh[0], bh[1]);
                    MMA(acc[mt][np*2+1], ah[mt], bh[2], bh[3]);
                    MMA(acc[mt][np*2],   ah[mt], bl[0], bl[1]);
                    MMA(acc[mt][np*2+1], ah[mt], bl[2], bl[3]);
                    MMA(acc[mt][np*2],   al[mt], bh[0], bh[1]);
                    MMA(acc[mt][np*2+1], al[mt], bh[2], bh[3]);
                }
            }
        }
    }

    const int pxb = pxt*128 + wm*32;
    #pragma unroll
    for (int mt = 0; mt < 2; mt++)
        #pragma unroll
        for (int nt = 0; nt < 8; nt++) {
            const int ocl = wn*64 + nt*8 + 2*tig;
            const float2 sc = *(float2*)&s_sc[ocl];
            const float2 bi = *(float2*)&s_bi[ocl];
            #pragma unroll
            for (int r = 0; r < 2; r++) {
                const int px = pxb + mt*16 + g + r*8;
                float vx = acc[mt][nt][r*2]   * sc.x + bi.x;
                float vy = acc[mt][nt][r*2+1] * sc.y + bi.y;
                const size_t base = (size_t)(cam*NPIX + px)*256 + ocl;
                if (MODE == 0) {
                    const float2 gt = *(float2*)&s_gt[ocl];
                    vx = fmaxf(vx, 0.f)*gt.x; vy = fmaxf(vy, 0.f)*gt.y;
                    *(float2*)&outf[base] = make_float2(vx, vy);
                } else if (MODE == 1) {
                    vx = fmaxf(vx, 0.f); vy = fmaxf(vy, 0.f);
                } else {
                    const float2 r0 = *(const float2*)&res[base];
                    vx = fmaxf(vx + r0.x, 0.f); vy = fmaxf(vy + r0.y, 0.f);
                    *(float2*)&outf[base] = make_float2(vx, vy);
                }
                if (MODE != 3) {
                    const __nv_bfloat16 h0 = __float2bfloat16(vx), h1 = __float2bfloat16(vy);
                    const uint32_t hp = (uint32_t)__bfloat16_as_ushort(h0)
                                      | ((uint32_t)__bfloat16_as_ushort(h1) << 16);
                    const uint32_t lp =
                          (uint32_t)__bfloat16_as_ushort(__float2bfloat16(vx - __bfloat162float(h0)))
                        | ((uint32_t)__bfloat16_as_ushort(__float2bfloat16(vy - __bfloat162float(h1))) << 16);
                    *(uint32_t*)&outh[base] = hp;
                    *(uint32_t*)&outl[base] = lp;
                }
            }
        }
}

// depth conv + softmax, weights cached in smem, 8 px/block; dp [cam][pix][bin]
#define DS_SMEM (112*257*4 + 8*256*4 + 64)
__global__ __launch_bounds__(128)
void depth_softmax_kernel(const float* __restrict__ x,
                          const float* __restrict__ w, const float* __restrict__ b,
                          float* __restrict__ dp)
{
    extern __shared__ float ds[];
    float* sw  = ds;
    float* sx  = ds + 112*257;
    float* red = sx + 8*256;
    const int blk = blockIdx.x;
    const int cam = (blk*8) / NPIX, p0 = (blk*8) % NPIX;
    const int tid = threadIdx.x, lane = tid & 31, wrp = tid >> 5;

    for (int i = tid; i < 112*256; i += 128) {
        const int bin = i >> 8, c = i & 255;
        sw[bin*257 + c] = w[i];
    }
    const float* xc = x + ((size_t)cam*NPIX + p0) * 256;
    for (int i = tid; i < 512; i += 128)
        *(float4*)&sx[i*4] = *(const float4*)&xc[i*4];
    __syncthreads();

    const float bb = (tid < DBINS) ? b[tid] : 0.f;
    #pragma unroll 1
    for (int pp = 0; pp < 8; pp++) {
        float lg = -1e30f;
        if (tid < DBINS) {
            float a0 = 0.f, a1 = 0.f, a2 = 0.f, a3 = 0.f;
            const float* wr = sw + tid*257;
            const float* xr = sx + pp*256;
            #pragma unroll 8
            for (int c = 0; c < 256; c += 4) {
                a0 = fmaf(xr[c],   wr[c],   a0);
                a1 = fmaf(xr[c+1], wr[c+1], a1);
                a2 = fmaf(xr[c+2], wr[c+2], a2);
                a3 = fmaf(xr[c+3], wr[c+3], a3);
            }
            lg = (a0 + a1) + (a2 + a3) + bb;
        }
        float m = lg;
        #pragma unroll
        for (int o = 16; o; o >>= 1) m = fmaxf(m, __shfl_xor_sync(0xffffffffu, m, o));
        if (lane == 0) red[wrp] = m;
        __syncthreads();
        m = fmaxf(fmaxf(red[0], red[1]), fmaxf(red[2], red[3]));
        __syncthreads();
        const float e = (tid < DBINS) ? __expf(lg - m) : 0.f;
        float s = e;
        #pragma unroll
        for (int o = 16; o; o >>= 1) s += __shfl_xor_sync(0xffffffffu, s, o);
        if (lane == 0) red[wrp] = s;
        __syncthreads();
        s = red[0] + red[1] + red[2] + red[3];
        __syncthreads();
        if (tid < DBINS)
            dp[((size_t)cam*NPIX + p0 + pp)*DBINS + tid] = e / s;   // coalesced
    }
}

// trilinear sample; dp [cam][pix][bin] — zi-adjacent taps share a sector
__global__ __launch_bounds__(256)
void sample_kernel(const float* __restrict__ grid, const float* __restrict__ dp,
                   float* __restrict__ out)
{
    const int v = blockIdx.x * blockDim.x + threadIdx.x;
    if (v >= NVOX) return;
    float agg = 0.f, mask = 0.f;
    #pragma unroll 1
    for (int cam = 0; cam < NCAM; cam++) {
        const float* g = grid + ((size_t)cam * NVOX + v) * 3;
        const float ix = ((g[0] + 1.f) * 88.f  - 1.f) * 0.5f;
        const float iy = ((g[1] + 1.f) * 32.f  - 1.f) * 0.5f;
        const float iz = ((g[2] + 1.f) * 112.f - 1.f) * 0.5f;
        const float fx0 = floorf(ix), fy0 = floorf(iy), fz0 = floorf(iz);
        const float fx = ix - fx0, fy = iy - fy0, fz = iz - fz0;
        const int x0 = (int)fx0, y0 = (int)fy0, z0 = (int)fz0;
        const float* dc = dp + (size_t)cam * NPIX * DBINS;
        #pragma unroll
        for (int dy = 0; dy < 2; dy++)
            #pragma unroll
            for (int dx = 0; dx < 2; dx++) {
                const int xi = x0 + dx, yi = y0 + dy;
                if ((unsigned)xi < 88u && (unsigned)yi < 32u) {
                    const float wxy = (dx ? fx : 1.f-fx) * (dy ? fy : 1.f-fy);
                    const float* dr = dc + (size_t)(yi*88 + xi) * DBINS;
                    #pragma unroll
                    for (int dz = 0; dz < 2; dz++) {
                        const int zi = z0 + dz;
                        const float wv = wxy * (dz ? fz : 1.f-fz);
                        if ((unsigned)zi < 112u) {
                            agg  += wv * dr[zi];
                            mask += wv;
                        }
                    }
                }
            }
    }
    out[v] = (mask > 0.f) ? (agg / mask) : agg;
}

extern "C" void kernel_launch(void* const* d_in, const int* in_sizes, int n_in,
                              void* d_out, int out_size)
{
    const float* img    = (const float*)d_in[0];
    const float* intr   = (const float*)d_in[1];
    const float* grid   = (const float*)d_in[2];
    const float* red_w  = (const float*)d_in[3];
    const float* red_s  = (const float*)d_in[4];
    const float* red_b  = (const float*)d_in[5];
    const float* mlp_w1 = (const float*)d_in[6];
    const float* mlp_b1 = (const float*)d_in[7];
    const float* mlp_w2 = (const float*)d_in[8];
    const float* mlp_b2 = (const float*)d_in[9];
    const float* se_rw  = (const float*)d_in[10];
    const float* se_rb  = (const float*)d_in[11];
    const float* se_ew  = (const float*)d_in[12];
    const float* se_eb  = (const float*)d_in[13];
    const float* bb_w   = (const float*)d_in[14];
    const float* bb_s   = (const float*)d_in[15];
    const float* bb_b   = (const float*)d_in[16];
    const float* dp_w   = (const float*)d_in[17];
    const float* dp_b   = (const float*)d_in[18];

    float *pxf, *pdp, *pg;
    __nv_bfloat16 *pih, *pil, *pxh, *pxl, *pyh, *pyl;
    cudaGetSymbolAddress((void**)&pxf, g_xf);
    cudaGetSymbolAddress((void**)&pdp, g_dp);
    cudaGetSymbolAddress((void**)&pg,  g_gate);
    cudaGetSymbolAddress((void**)&pih, g_imgh);
    cudaGetSymbolAddress((void**)&pil, g_imgl);
    cudaGetSymbolAddress((void**)&pxh, g_xh);
    cudaGetSymbolAddress((void**)&pxl, g_xl);
    cudaGetSymbolAddress((void**)&pyh, g_yh);
    cudaGetSymbolAddress((void**)&pyl, g_yl);

    cudaFuncSetAttribute(conv_kernel<512,0>, cudaFuncAttributeMaxDynamicSharedMemorySize, CONV_SMEM);
    cudaFuncSetAttribute(conv_kernel<256,1>, cudaFuncAttributeMaxDynamicSharedMemorySize, CONV_SMEM);
    cudaFuncSetAttribute(conv_kernel<256,2>, cudaFuncAttributeMaxDynamicSharedMemorySize, CONV_SMEM);
    cudaFuncSetAttribute(conv_kernel<256,3>, cudaFuncAttributeMaxDynamicSharedMemorySize, CONV_SMEM);
    cudaFuncSetAttribute(depth_softmax_kernel, cudaFuncAttributeMaxDynamicSharedMemorySize, DS_SMEM);

    gate_kernel<<<NCAM, 256>>>(intr, mlp_w1, mlp_b1, mlp_w2, mlp_b2,
                               se_rw, se_rb, se_ew, se_eb, pg);
    prep_img_kernel<<<dim3(22, 8, NCAM), 256>>>(img);
    wtrans_kernel<<<(WHT*128*64 + 255)/256, 256>>>(red_w, bb_w);

    dim3 cg(22, 1, NCAM);
    conv_kernel<512,0><<<cg, 512, CONV_SMEM>>>(pih, pil, 0, red_s, red_b, pg,
                                               nullptr, pxf, pxh, pxl);
    for (int i = 0; i < 3; i++) {
        conv_kernel<256,1><<<cg, 512, CONV_SMEM>>>(pxh, pxl, 144 + (2*i)*72,
            bb_s + (2*i)*MID, bb_b + (2*i)*MID, nullptr, nullptr, nullptr, pyh, pyl);
        if (i < 2)
            conv_kernel<256,2><<<cg, 512, CONV_SMEM>>>(pyh, pyl, 144 + (2*i+1)*72,
                bb_s + (2*i+1)*MID, bb_b + (2*i+1)*MID, nullptr, pxf, pxf, pxh, pxl);
        else
            conv_kernel<256,3><<<cg, 512, CONV_SMEM>>>(pyh, pyl, 144 + (2*i+1)*72,
                bb_s + (2*i+1)*MID, bb_b + (2*i+1)*MID, nullptr, pxf, pxf, pxh, pxl);
    }
    depth_softmax_kernel<<<NCAM * NPIX / 8, 128, DS_SMEM>>>(pxf, dp_w, dp_b, pdp);
    sample_kernel<<<(NVOX + 255)/256, 256>>>(grid, pdp, (float*)d_out);
}

// round 13
// speedup vs baseline: 1.4413x; 1.1716x over previous
#include <cuda_runtime.h>
#include <cuda_bf16.h>
#include <math.h>
#include <stdint.h>

#define NCAM 6
#define MID 256
#define DBINS 112
#define HH 32
#define WW 88
#define NPIX 2816
#define NVOX (128*128*16)
#define WHT 576                 // conv tiles; depth tiles at 576..579

__device__ __align__(1024) float g_xf [NCAM*NPIX*MID];
__device__ __align__(1024) float g_dp [NCAM*NPIX*DBINS];
__device__ __align__(1024) float g_gate[NCAM*MID];
__device__ __align__(1024) __nv_bfloat16 g_imgh[NCAM*NPIX*512];
__device__ __align__(1024) __nv_bfloat16 g_imgl[NCAM*NPIX*512];
__device__ __align__(1024) __nv_bfloat16 g_xh[NCAM*NPIX*MID];
__device__ __align__(1024) __nv_bfloat16 g_xl[NCAM*NPIX*MID];
__device__ __align__(1024) __nv_bfloat16 g_yh[NCAM*NPIX*MID];
__device__ __align__(1024) __nv_bfloat16 g_yl[NCAM*NPIX*MID];
__device__ __align__(1024) __nv_bfloat16 g_Wh[(WHT+4)*128*64];
__device__ __align__(1024) __nv_bfloat16 g_Wl[(WHT+4)*128*64];

__device__ __forceinline__ uint32_t smem_u32(const void* p) {
    uint32_t a;
    asm("{ .reg .u64 t; cvta.to.shared.u64 t, %1; cvt.u32.u64 %0, t; }" : "=r"(a) : "l"(p));
    return a;
}
#define SW128(o) ((o) ^ (((o) >> 3) & 0x70))
#define LDM4(r0,r1,r2,r3,addr) \
    asm volatile("ldmatrix.sync.aligned.m8n8.x4.shared.b16 {%0,%1,%2,%3}, [%4];" \
        : "=r"(r0),"=r"(r1),"=r"(r2),"=r"(r3) : "r"(addr))
#define MMA(d,a,b0,b1) \
    asm volatile("mma.sync.aligned.m16n8k16.row.col.f32.bf16.bf16.f32 " \
        "{%0,%1,%2,%3},{%4,%5,%6,%7},{%8,%9},{%0,%1,%2,%3};" \
        : "+f"((d)[0]),"+f"((d)[1]),"+f"((d)[2]),"+f"((d)[3]) \
        : "r"((a)[0]),"r"((a)[1]),"r"((a)[2]),"r"((a)[3]),"r"(b0),"r"(b1))
__device__ __forceinline__ void cpa16(uint32_t dst, const void* src, int sz) {
    asm volatile("cp.async.cg.shared.global [%0], [%1], 16, %2;" :: "r"(dst), "l"(src), "r"(sz) : "memory");
}
#define CPA_COMMIT() asm volatile("cp.async.commit_group;" ::: "memory")
#define CPA_WAIT0()  asm volatile("cp.async.wait_group 0;" ::: "memory")

__device__ __forceinline__ uint32_t pack_hi(float a, float b, uint32_t &lo) {
    const __nv_bfloat16 h0 = __float2bfloat16(a), h1 = __float2bfloat16(b);
    lo = (uint32_t)__bfloat16_as_ushort(__float2bfloat16(a - __bfloat162float(h0)))
       | ((uint32_t)__bfloat16_as_ushort(__float2bfloat16(b - __bfloat162float(h1))) << 16);
    return (uint32_t)__bfloat16_as_ushort(h0) | ((uint32_t)__bfloat16_as_ushort(h1) << 16);
}

// img [cam][512][px] f32 -> [cam][px][512] bf16 hi/lo
__global__ __launch_bounds__(256) void prep_img_kernel(const float* __restrict__ img)
{
    __shared__ float st[64][129];
    const int px0 = blockIdx.x * 128, cg = blockIdx.y, cam = blockIdx.z;
    const int tid = threadIdx.x;
    for (int i = tid; i < 64*128; i += 256) {
        const int c = i >> 7, p = i & 127;
        st[c][p] = img[((size_t)cam*512 + cg*64 + c)*NPIX + px0 + p];
    }
    __syncthreads();
    for (int i = tid; i < 128*16; i += 256) {
        const int p = i >> 4, c4 = (i & 15) * 4;
        uint2 hp, lp;
        hp.x = pack_hi(st[c4][p],   st[c4+1][p], lp.x);
        hp.y = pack_hi(st[c4+2][p], st[c4+3][p], lp.y);
        const size_t o = ((size_t)(cam*NPIX + px0 + p))*512 + cg*64 + c4;
        *(uint2*)&g_imgh[o] = hp;
        *(uint2*)&g_imgl[o] = lp;
    }
}

// weight transform, coalesced reads: block loads OCG oc * CIN*9 contiguous floats
template<int CIN>
__global__ __launch_bounds__(256) void wtrans2_kernel(const float* __restrict__ w, int htBase)
{
    constexpr int OCG = (CIN == 512) ? 4 : 8;
    constexpr int PER_OC = CIN * 9;
    constexpr int CIG = CIN / 64;
    extern __shared__ float s[];                 // OCG*PER_OC = 18432 floats (72KB)
    const int ocbase = blockIdx.x * OCG;
    const int layer  = blockIdx.y;
    const int tid = threadIdx.x;
    const int htB = htBase + layer * (CIG * 18);

    const float4* src = (const float4*)(w + (size_t)layer*256*PER_OC + (size_t)ocbase*PER_OC);
    for (int i = tid; i < OCG*PER_OC/4; i += 256) ((float4*)s)[i] = src[i];
    __syncthreads();

    const int half = ocbase >> 7;
    for (int t = tid; t < OCG*PER_OC/2; t += 256) {
        const int ci2 = t & 31, rowidx = t >> 5;
        const int oc_l = rowidx / (CIG*9);
        const int r2 = rowidx - oc_l*(CIG*9);
        const int cig = r2 / 9, tap = r2 - cig*9;
        const int ci = ci2*2;
        const float w0 = s[oc_l*PER_OC + (cig*64 + ci)*9 + tap];
        const float w1 = s[oc_l*PER_OC + (cig*64 + ci + 1)*9 + tap];
        uint32_t lo;
        const uint32_t hi = pack_hi(w0, w1, lo);
        const int ocl = (ocbase + oc_l) & 127;
        const int ht = htB + (tap*CIG + cig)*2 + half;
        const size_t off = (size_t)ht*16384 + SW128((uint32_t)(ocl*128 + ci*2));
        *(uint32_t*)((char*)g_Wh + off) = hi;
        *(uint32_t*)((char*)g_Wl + off) = lo;
    }
}

// depth weights [112][256] -> 4 tiles (128x64), bins>=112 zero
__global__ __launch_bounds__(256) void dtrans_kernel(const float* __restrict__ dw)
{
    const int t = blockIdx.x*256 + threadIdx.x;
    if (t >= 4*128*32) return;
    const int ci2 = t & 31, r = (t >> 5) & 127, c = t >> 12;
    const int ci = ci2*2;
    float w0 = 0.f, w1 = 0.f;
    if (r < DBINS) { w0 = dw[r*256 + c*64 + ci]; w1 = dw[r*256 + c*64 + ci + 1]; }
    uint32_t lo;
    const uint32_t hi = pack_hi(w0, w1, lo);
    const size_t off = (size_t)(WHT + c)*16384 + SW128((uint32_t)(r*128 + ci*2));
    *(uint32_t*)((char*)g_Wh + off) = hi;
    *(uint32_t*)((char*)g_Wl + off) = lo;
}

__global__ void gate_kernel(const float* __restrict__ intr,
                            const float* __restrict__ w1, const float* __restrict__ b1,
                            const float* __restrict__ w2, const float* __restrict__ b2,
                            const float* __restrict__ rw, const float* __restrict__ rb,
                            const float* __restrict__ ew, const float* __restrict__ eb,
                            float* __restrict__ gate)
{
    int cam = blockIdx.x, tid = threadIdx.x;
    __shared__ float sp_s, h[256], h2[256], t[256];
    if (tid == 0) {
        double A[4][8];
        for (int r = 0; r < 4; r++) {
            for (int c = 0; c < 4; c++) A[r][c] = (double)intr[cam*16 + r*4 + c];
            for (int c = 0; c < 4; c++) A[r][4+c] = (r == c) ? 1.0 : 0.0;
        }
        for (int col = 0; col < 4; col++) {
            int piv = col; double best = fabs(A[col][col]);
            for (int r = col+1; r < 4; r++)
                if (fabs(A[r][col]) > best) { best = fabs(A[r][col]); piv = r; }
            if (piv != col)
                for (int c = 0; c < 8; c++) { double tmp = A[col][c]; A[col][c] = A[piv][c]; A[piv][c] = tmp; }
            double d = A[col][col];
            for (int c = 0; c < 8; c++) A[col][c] /= d;
            for (int r = 0; r < 4; r++) if (r != col) {
                double f = A[r][col];
                for (int c = 0; c < 8; c++) A[r][c] -= f * A[col][c];
            }
        }
        sp_s = (float)(1000.0 * sqrt(A[0][4]*A[0][4] + A[1][5]*A[1][5]));
    }
    __syncthreads();
    float sp = sp_s;
    h[tid] = fmaxf(sp * w1[tid] + b1[tid], 0.f);
    __syncthreads();
    float s = b2[tid];
    for (int k = 0; k < 256; k++) s += h[k] * w2[k*256 + tid];
    h2[tid] = s;
    __syncthreads();
    s = rb[tid];
    for (int c = 0; c < 256; c++) s += rw[tid*256 + c] * h2[c];
    t[tid] = fmaxf(s, 0.f);
    __syncthreads();
    s = eb[tid];
    for (int c = 0; c < 256; c++) s += ew[tid*256 + c] * t[c];
    gate[cam*256 + tid] = 1.f / (1.f + __expf(-s));
}

// HMMA conv: 128px x 256oc, 16 warps, warp tile 32x64. Grid (22,1,6).
// MODE 0: relu*gate f32+split; 1: relu split; 2: relu(res+) f32+split; 4: relu(res+) split only
#define BUF 98304
#define CONV_SMEM (4096 + 2*BUF)
template<int CIN, int MODE>
__global__ void __launch_bounds__(512, 1)
conv_kernel(const __nv_bfloat16* __restrict__ inh, const __nv_bfloat16* __restrict__ inl,
            int aoff,
            const float* __restrict__ scale, const float* __restrict__ bias,
            const float* __restrict__ gate,  const float* res,
            float* outf, __nv_bfloat16* __restrict__ outh, __nv_bfloat16* __restrict__ outl)
{
    constexpr int CIG = CIN / 64, NCH = 9 * CIG;
    extern __shared__ __align__(1024) char smem[];
    float* s_sc = (float*)smem;
    float* s_bi = (float*)(smem + 1024);
    float* s_gt = (float*)(smem + 2048);
    const uint32_t sb0 = smem_u32(smem) + 4096;

    const int pxt = blockIdx.x, cam = blockIdx.z;
    const int tid = threadIdx.x, wid = tid >> 5, lane = tid & 31;
    const int wm = wid & 3, wn = wid >> 2;
    const int g = lane >> 2, tig = lane & 3;

    if (tid < 256) {
        s_sc[tid] = scale[tid];
        s_bi[tid] = bias [tid];
        s_gt[tid] = (MODE == 0) ? gate[cam*256 + tid] : 0.f;
    }

    float acc[2][8][4];
    #pragma unroll
    for (int a = 0; a < 2; a++)
        #pragma unroll
        for (int b = 0; b < 8; b++)
            #pragma unroll
            for (int c = 0; c < 4; c++) acc[a][b][c] = 0.f;

    const int arow = wm*32 + (lane & 15);
    const int ak16 = (lane >> 4) << 4;
    const int brow = wn*64 + (lane & 7) + ((lane >> 4) << 3);
    const int bk16 = ((lane >> 3) & 1) << 4;

    auto stage = [&](int j, int b) {
        const uint32_t dA = sb0 + b*BUF, dB = dA + 32768;
        const char* sH = (const char*)g_Wh + (size_t)(aoff + j*2) * 16384;
        const char* sL = (const char*)g_Wl + (size_t)(aoff + j*2) * 16384;
        #pragma unroll
        for (int t = 0; t < 4; t++) {
            const uint32_t o = (tid + 512*t) * 16;
            cpa16(dB + o,         sH + o, 16);
            cpa16(dB + 32768 + o, sL + o, 16);
        }
        const int tap = j / CIG, cig = j - tap*CIG;
        const int dh = tap/3 - 1, dw = tap%3 - 1;
        #pragma unroll
        for (int t = 0; t < 2; t++) {
            const int u = tid + 512*t;
            const int px = u >> 3, q = u & 7;
            const int p = pxt*128 + px;
            const int h = p/88 + dh, w = p - (p/88)*88 + dw;
            const bool ok = ((unsigned)h < 32u) & ((unsigned)w < 88u);
            const size_t s0 = ok ? (((size_t)(cam*NPIX + h*88 + w))*CIN + cig*64 + q*8) : 0;
            const int sz = ok ? 16 : 0;
            const uint32_t sw = SW128((uint32_t)(px*128 + q*16));
            cpa16(dA + sw,         inh + s0, sz);
            cpa16(dA + 16384 + sw, inl + s0, sz);
        }
        CPA_COMMIT();
    };

    stage(0, 0);
    #pragma unroll 1
    for (int j = 0; j < NCH; j++) {
        const int b = j & 1;
        CPA_WAIT0();
        __syncthreads();
        if (j + 1 < NCH) stage(j + 1, 1 - b);

        const uint32_t sbA = sb0 + b*BUF, sbB = sbA + 32768;
        #pragma unroll
        for (int ks = 0; ks < 4; ks++) {
            uint32_t ah[2][4], al[2][4];
            #pragma unroll
            for (int mt = 0; mt < 2; mt++) {
                const uint32_t off = (uint32_t)((arow + mt*16)*128 + ks*32) + ak16;
                LDM4(ah[mt][0],ah[mt][1],ah[mt][2],ah[mt][3], sbA + SW128(off));
                LDM4(al[mt][0],al[mt][1],al[mt][2],al[mt][3], sbA + 16384 + SW128(off));
            }
            #pragma unroll
            for (int np = 0; np < 4; np++) {
                uint32_t bh[4], bl[4];
                const uint32_t boff = (uint32_t)((brow + np*16)*128 + ks*32) + bk16;
                LDM4(bh[0],bh[1],bh[2],bh[3], sbB + SW128(boff));
                LDM4(bl[0],bl[1],bl[2],bl[3], sbB + 32768 + SW128(boff));
                #pragma unroll
                for (int mt = 0; mt < 2; mt++) {
                    MMA(acc[mt][np*2],   ah[mt], bh[0], bh[1]);
                    MMA(acc[mt][np*2+1], ah[mt], bh[2], bh[3]);
                    MMA(acc[mt][np*2],   ah[mt], bl[0], bl[1]);
                    MMA(acc[mt][np*2+1], ah[mt], bl[2], bl[3]);
                    MMA(acc[mt][np*2],   al[mt], bh[0], bh[1]);
                    MMA(acc[mt][np*2+1], al[mt], bh[2], bh[3]);
                }
            }
        }
    }

    const int pxb = pxt*128 + wm*32;
    #pragma unroll
    for (int mt = 0; mt < 2; mt++)
        #pragma unroll
        for (int nt = 0; nt < 8; nt++) {
            const int ocl = wn*64 + nt*8 + 2*tig;
            const float2 sc = *(float2*)&s_sc[ocl];
            const float2 bi = *(float2*)&s_bi[ocl];
            #pragma unroll
            for (int r = 0; r < 2; r++) {
                const int px = pxb + mt*16 + g + r*8;
                float vx = acc[mt][nt][r*2]   * sc.x + bi.x;
                float vy = acc[mt][nt][r*2+1] * sc.y + bi.y;
                const size_t base = (size_t)(cam*NPIX + px)*256 + ocl;
                if (MODE == 0) {
                    const float2 gt = *(float2*)&s_gt[ocl];
                    vx = fmaxf(vx, 0.f)*gt.x; vy = fmaxf(vy, 0.f)*gt.y;
                } else if (MODE == 1) {
                    vx = fmaxf(vx, 0.f); vy = fmaxf(vy, 0.f);
                } else {
                    const float2 r0 = *(const float2*)&res[base];
                    vx = fmaxf(vx + r0.x, 0.f); vy = fmaxf(vy + r0.y, 0.f);
                }
                if (MODE == 0 || MODE == 2)
                    *(float2*)&outf[base] = make_float2(vx, vy);
                uint32_t lo;
                const uint32_t hi = pack_hi(vx, vy, lo);
                *(uint32_t*)&outh[base] = hi;
                *(uint32_t*)&outl[base] = lo;
            }
        }
}

// depth logits via HMMA + fused softmax. Grid (22,1,6), 256 thr (8 warps: 4px x 2bin).
#define LBUF 65536
#define LG_SMEM (1024 + 2*LBUF)
__global__ void __launch_bounds__(256, 1)
logit_softmax_kernel(const __nv_bfloat16* __restrict__ xh, const __nv_bfloat16* __restrict__ xl,
                     const float* __restrict__ bias, float* __restrict__ dp)
{
    extern __shared__ __align__(1024) char smem[];
    float* s_bi = (float*)smem;
    const uint32_t sb0 = smem_u32(smem) + 1024;
    float* slog = (float*)(smem + 1024);        // [128][132] after compute

    const int pxt = blockIdx.x, cam = blockIdx.z;
    const int tid = threadIdx.x, wid = tid >> 5, lane = tid & 31;
    const int wm = wid & 3, wn = wid >> 2;      // wn 0..1
    const int g = lane >> 2, tig = lane & 3;
    const int campix0 = cam*NPIX + pxt*128;

    if (tid < 128) s_bi[tid] = (tid < DBINS) ? bias[tid] : 0.f;

    float acc[2][8][4];
    #pragma unroll
    for (int a = 0; a < 2; a++)
        #pragma unroll
        for (int b = 0; b < 8; b++)
            #pragma unroll
            for (int c = 0; c < 4; c++) acc[a][b][c] = 0.f;

    const int arow = wm*32 + (lane & 15);
    const int ak16 = (lane >> 4) << 4;
    const int brow = wn*64 + (lane & 7) + ((lane >> 4) << 3);
    const int bk16 = ((lane >> 3) & 1) << 4;

    auto stage = [&](int c, int b) {
        const uint32_t dA = sb0 + b*LBUF, dB = dA + 32768;
        const char* sH = (const char*)g_Wh + (size_t)(WHT + c)*16384;
        const char* sL = (const char*)g_Wl + (size_t)(WHT + c)*16384;
        #pragma unroll
        for (int t = 0; t < 4; t++) {
            const uint32_t o = (tid + 256*t) * 16;
            cpa16(dB + o,         sH + o, 16);
            cpa16(dB + 16384 + o, sL + o, 16);
        }
        #pragma unroll
        for (int t = 0; t < 4; t++) {
            const int u = tid + 256*t;
            const int px = u >> 3, q = u & 7;
            const size_t s0 = (size_t)(campix0 + px)*256 + c*64 + q*8;
            const uint32_t sw = SW128((uint32_t)(px*128 + q*16));
            cpa16(dA + sw,         xh + s0, 16);
            cpa16(dA + 16384 + sw, xl + s0, 16);
        }
        CPA_COMMIT();
    };

    stage(0, 0);
    #pragma unroll 1
    for (int c = 0; c < 4; c++) {
        const int b = c & 1;
        CPA_WAIT0();
        __syncthreads();
        if (c + 1 < 4) stage(c + 1, 1 - b);

        const uint32_t sbA = sb0 + b*LBUF, sbB = sbA + 32768;
        #pragma unroll
        for (int ks = 0; ks < 4; ks++) {
            uint32_t ah[2][4], al[2][4];
            #pragma unroll
            for (int mt = 0; mt < 2; mt++) {
                const uint32_t off = (uint32_t)((arow + mt*16)*128 + ks*32) + ak16;
                LDM4(ah[mt][0],ah[mt][1],ah[mt][2],ah[mt][3], sbA + SW128(off));
                LDM4(al[mt][0],al[mt][1],al[mt][2],al[mt][3], sbA + 16384 + SW128(off));
            }
            #pragma unroll
            for (int np = 0; np < 4; np++) {
                uint32_t bh[4], bl[4];
                const uint32_t boff = (uint32_t)((brow + np*16)*128 + ks*32) + bk16;
                LDM4(bh[0],bh[1],bh[2],bh[3], sbB + SW128(boff));
                LDM4(bl[0],bl[1],bl[2],bl[3], sbB + 16384 + SW128(boff));
                #pragma unroll
                for (int mt = 0; mt < 2; mt++) {
                    MMA(acc[mt][np*2],   ah[mt], bh[0], bh[1]);
                    MMA(acc[mt][np*2+1], ah[mt], bh[2], bh[3]);
                    MMA(acc[mt][np*2],   ah[mt], bl[0], bl[1]);
                    MMA(acc[mt][np*2+1], ah[mt], bl[2], bl[3]);
                    MMA(acc[mt][np*2],   al[mt], bh[0], bh[1]);
                    MMA(acc[mt][np*2+1], al[mt], bh[2], bh[3]);
                }
            }
        }
    }
    __syncthreads();   // buffers dead; slog overlays them

    #pragma unroll
    for (int mt = 0; mt < 2; mt++)
        #pragma unroll
        for (int nt = 0; nt < 8; nt++) {
            const int n = wn*64 + nt*8 + 2*tig;
            #pragma unroll
            for (int r = 0; r < 2; r++) {
                const int px = wm*32 + mt*16 + g + r*8;
                *(float2*)&slog[px*132 + n] =
                    make_float2(acc[mt][nt][r*2] + s_bi[n], acc[mt][nt][r*2+1] + s_bi[n+1]);
            }
        }
    __syncthreads();

    // softmax: 2 threads per px (part 0: bins 0..63, part 1: bins 64..111)
    const int px = tid >> 1, part = tid & 1;
    const float* row = &slog[px*132 + part*64];
    const int cnt = part ? 48 : 64;
    float m = -1e30f;
    for (int i = 0; i < cnt; i++) m = fmaxf(m, row[i]);
    m = fmaxf(m, __shfl_xor_sync(0xffffffffu, m, 1));
    float s = 0.f;
    for (int i = 0; i < cnt; i++) s += __expf(row[i] - m);
    s += __shfl_xor_sync(0xffffffffu, s, 1);
    const float inv = 1.f / s;
    float* drow = &dp[(size_t)(campix0 + px)*DBINS + part*64];
    for (int i = 0; i < cnt; i++) drow[i] = __expf(row[i] - m) * inv;
}

// trilinear sample; dp [cam][pix][bin]
__global__ __launch_bounds__(256)
void sample_kernel(const float* __restrict__ grid, const float* __restrict__ dp,
                   float* __restrict__ out)
{
    const int v = blockIdx.x * blockDim.x + threadIdx.x;
    if (v >= NVOX) return;
    float agg = 0.f, mask = 0.f;
    #pragma unroll 1
    for (int cam = 0; cam < NCAM; cam++) {
        const float* g = grid + ((size_t)cam * NVOX + v) * 3;
        const float ix = ((g[0] + 1.f) * 88.f  - 1.f) * 0.5f;
        const float iy = ((g[1] + 1.f) * 32.f  - 1.f) * 0.5f;
        const float iz = ((g[2] + 1.f) * 112.f - 1.f) * 0.5f;
        const float fx0 = floorf(ix), fy0 = floorf(iy), fz0 = floorf(iz);
        const float fx = ix - fx0, fy = iy - fy0, fz = iz - fz0;
        const int x0 = (int)fx0, y0 = (int)fy0, z0 = (int)fz0;
        const float* dc = dp + (size_t)cam * NPIX * DBINS;
        #pragma unroll
        for (int dy = 0; dy < 2; dy++)
            #pragma unroll
            for (int dx = 0; dx < 2; dx++) {
                const int xi = x0 + dx, yi = y0 + dy;
                if ((unsigned)xi < 88u && (unsigned)yi < 32u) {
                    const float wxy = (dx ? fx : 1.f-fx) * (dy ? fy : 1.f-fy);
                    const float* dr = dc + (size_t)(yi*88 + xi) * DBINS;
                    #pragma unroll
                    for (int dz = 0; dz < 2; dz++) {
                        const int zi = z0 + dz;
                        const float wv = wxy * (dz ? fz : 1.f-fz);
                        if ((unsigned)zi < 112u) { agg += wv * dr[zi]; mask += wv; }
                    }
                }
            }
    }
    out[v] = (mask > 0.f) ? (agg / mask) : agg;
}

extern "C" void kernel_launch(void* const* d_in, const int* in_sizes, int n_in,
                              void* d_out, int out_size)
{
    const float* img    = (const float*)d_in[0];
    const float* intr   = (const float*)d_in[1];
    const float* grid   = (const float*)d_in[2];
    const float* red_w  = (const float*)d_in[3];
    const float* red_s  = (const float*)d_in[4];
    const float* red_b  = (const float*)d_in[5];
    const float* mlp_w1 = (const float*)d_in[6];
    const float* mlp_b1 = (const float*)d_in[7];
    const float* mlp_w2 = (const float*)d_in[8];
    const float* mlp_b2 = (const float*)d_in[9];
    const float* se_rw  = (const float*)d_in[10];
    const float* se_rb  = (const float*)d_in[11];
    const float* se_ew  = (const float*)d_in[12];
    const float* se_eb  = (const float*)d_in[13];
    const float* bb_w   = (const float*)d_in[14];
    const float* bb_s   = (const float*)d_in[15];
    const float* bb_b   = (const float*)d_in[16];
    const float* dp_w   = (const float*)d_in[17];
    const float* dp_b   = (const float*)d_in[18];

    float *pxf, *pdp, *pg;
    __nv_bfloat16 *pih, *pil, *pxh, *pxl, *pyh, *pyl;
    cudaGetSymbolAddress((void**)&pxf, g_xf);
    cudaGetSymbolAddress((void**)&pdp, g_dp);
    cudaGetSymbolAddress((void**)&pg,  g_gate);
    cudaGetSymbolAddress((void**)&pih, g_imgh);
    cudaGetSymbolAddress((void**)&pil, g_imgl);
    cudaGetSymbolAddress((void**)&pxh, g_xh);
    cudaGetSymbolAddress((void**)&pxl, g_xl);
    cudaGetSymbolAddress((void**)&pyh, g_yh);
    cudaGetSymbolAddress((void**)&pyl, g_yl);

    cudaFuncSetAttribute(conv_kernel<512,0>, cudaFuncAttributeMaxDynamicSharedMemorySize, CONV_SMEM);
    cudaFuncSetAttribute(conv_kernel<256,1>, cudaFuncAttributeMaxDynamicSharedMemorySize, CONV_SMEM);
    cudaFuncSetAttribute(conv_kernel<256,2>, cudaFuncAttributeMaxDynamicSharedMemorySize, CONV_SMEM);
    cudaFuncSetAttribute(conv_kernel<256,4>, cudaFuncAttributeMaxDynamicSharedMemorySize, CONV_SMEM);
    cudaFuncSetAttribute(logit_softmax_kernel, cudaFuncAttributeMaxDynamicSharedMemorySize, LG_SMEM);
    cudaFuncSetAttribute(wtrans2_kernel<512>, cudaFuncAttributeMaxDynamicSharedMemorySize, 73728);
    cudaFuncSetAttribute(wtrans2_kernel<256>, cudaFuncAttributeMaxDynamicSharedMemorySize, 73728);

    gate_kernel<<<NCAM, 256>>>(intr, mlp_w1, mlp_b1, mlp_w2, mlp_b2,
                               se_rw, se_rb, se_ew, se_eb, pg);
    prep_img_kernel<<<dim3(22, 8, NCAM), 256>>>(img);
    wtrans2_kernel<512><<<dim3(64, 1), 256, 73728>>>(red_w, 0);
    wtrans2_kernel<256><<<dim3(32, 6), 256, 73728>>>(bb_w, 144);
    dtrans_kernel<<<64, 256>>>(dp_w);

    dim3 cg(22, 1, NCAM);
    conv_kernel<512,0><<<cg, 512, CONV_SMEM>>>(pih, pil, 0, red_s, red_b, pg,
                                               nullptr, pxf, pxh, pxl);
    for (int i = 0; i < 3; i++) {
        conv_kernel<256,1><<<cg, 512, CONV_SMEM>>>(pxh, pxl, 144 + (2*i)*72,
            bb_s + (2*i)*MID, bb_b + (2*i)*MID, nullptr, nullptr, nullptr, pyh, pyl);
        if (i < 2)
            conv_kernel<256,2><<<cg, 512, CONV_SMEM>>>(pyh, pyl, 144 + (2*i+1)*72,
                bb_s + (2*i+1)*MID, bb_b + (2*i+1)*MID, nullptr, pxf, pxf, pxh, pxl);
        else
            conv_kernel<256,4><<<cg, 512, CONV_SMEM>>>(pyh, pyl, 144 + (2*i+1)*72,
                bb_s + (2*i+1)*MID, bb_b + (2*i+1)*MID, nullptr, pxf, nullptr, pxh, pxl);
    }
    logit_softmax_kernel<<<cg, 256, LG_SMEM>>>(pxh, pxl, dp_b, pdp);
    sample_kernel<<<(NVOX + 255)/256, 256>>>(grid, pdp, (float*)d_out);
}